// round 10
// baseline (speedup 1.0000x reference)
#include <cuda_runtime.h>
#include <cstdint>

// ---------------------------------------------------------------------------
// MCNET binarized CNN (algebraic identities, see R0):
//   * sign(maxpool(hardtanh(v))) == sign(max(v))
//   * sign(hardtanh(int n)) == sign(n)
//   * L2..L4 activations are ternary {-1,0,+1} int8 sign maps
// R10: l2/l3/l4/prep frozen (R9). l1 only: fma.rn.f32x2 packed math
// (864 FFMA -> 432 FFMA2) + interior fast path (unpredicated loads).
// ---------------------------------------------------------------------------

static __device__ uint2 g_s1[32u * 256 * 256];         // [b,y,x, 8ch]  16.8 MB
static __device__ int4  g_s2[32u * 254 * 254];         // [b,y,x,16ch]  33.0 MB
static __device__ uint2 g_s3v[4][32u * 252 * 252];     // [plane][b,y,x] 8ch each

static __device__ float g_w1f[216];    // [o=8][c=3][ky][kx] as float +-1/0
static __device__ int   g_w2p[288];    // [o=16][9 pos][2 packs of 4ch]
static __device__ int   g_w3p[1152];   // [o=32][9 pos][4 packs of 4ch]
static __device__ int   g_w4p[144];    // [o=2 ][9 pos][8 packs of 4ch]

__device__ __forceinline__ int sgnf(float v) { return (v > 0.f) - (v < 0.f); }
__device__ __forceinline__ int sgni(int v)   { return (v > 0) - (v < 0); }
__device__ __forceinline__ int pack4(int a, int b, int c, int d) {
    return (a & 0xFF) | ((b & 0xFF) << 8) | ((c & 0xFF) << 16) | ((d & 0xFF) << 24);
}

// ---- packed f32x2 helpers (sm_100) ----------------------------------------
__device__ __forceinline__ unsigned long long pk2(float lo, float hi) {
    unsigned long long r;
    asm("mov.b64 %0, {%1, %2};" : "=l"(r) : "f"(lo), "f"(hi));
    return r;
}
__device__ __forceinline__ void upk2(unsigned long long v, float& lo, float& hi) {
    asm("mov.b64 {%0, %1}, %2;" : "=f"(lo), "=f"(hi) : "l"(v));
}
__device__ __forceinline__ unsigned long long ffma2(unsigned long long a,
                                                    unsigned long long b,
                                                    unsigned long long c) {
    unsigned long long d;
    asm("fma.rn.f32x2 %0, %1, %2, %3;" : "=l"(d) : "l"(a), "l"(b), "l"(c));
    return d;
}

// ---------------------------------------------------------------------------
__global__ void prep_kernel(const float* __restrict__ w1, const float* __restrict__ w2,
                            const float* __restrict__ w3, const float* __restrict__ w4) {
    int t = threadIdx.x;
    for (int i = t; i < 216; i += blockDim.x) g_w1f[i] = (float)sgnf(w1[i]);
    for (int i = t; i < 288; i += blockDim.x) {
        int h = i & 1, pos = (i >> 1) % 9, o = i / 18;
        int ky = pos / 3, kx = pos % 3;
        int s[4];
        #pragma unroll
        for (int j = 0; j < 4; j++)
            s[j] = sgnf(w2[((o * 8 + (4 * h + j)) * 3 + ky) * 3 + kx]);
        g_w2p[i] = pack4(s[0], s[1], s[2], s[3]);
    }
    for (int i = t; i < 1152; i += blockDim.x) {
        int q = i & 3, pos = (i >> 2) % 9, o = i / 36;
        int ky = pos / 3, kx = pos % 3;
        int s[4];
        #pragma unroll
        for (int j = 0; j < 4; j++)
            s[j] = sgnf(w3[((o * 16 + (4 * q + j)) * 3 + ky) * 3 + kx]);
        g_w3p[i] = pack4(s[0], s[1], s[2], s[3]);
    }
    for (int i = t; i < 144; i += blockDim.x) {
        int q = i & 7, pos = (i >> 3) % 9, o = i / 72;
        int ky = pos / 3, kx = pos % 3;
        int s[4];
        #pragma unroll
        for (int j = 0; j < 4; j++)
            s[j] = sgnf(w4[((o * 32 + (4 * q + j)) * 3 + ky) * 3 + kx]);
        g_w4p[i] = pack4(s[0], s[1], s[2], s[3]);
    }
}

// ---------------------------------------------------------------------------
// Layer 1: fp conv (3->8), pad 1.0, fused hardtanh+maxpool+sign.
// One thread = one pooled pixel, 8 oc. Packed f32x2 math: lo/hi lanes of each
// accumulator are the two x-adjacent pool positions (dx=0/1); acc_t holds
// dy=0, acc_b holds dy=1. Weights duplicated {w,w} in smem -> LDS.64 operand.
// Interior threads (98.4%) take an unpredicated load path.
// ---------------------------------------------------------------------------
__global__ __launch_bounds__(256)
void l1_kernel(const float* __restrict__ x) {
    __shared__ __align__(8) float swd[432];          // [idx*2 + {0,1}] = {w,w}
    for (int i = threadIdx.x; i < 216; i += 256) {
        float w = g_w1f[i];
        swd[2 * i] = w; swd[2 * i + 1] = w;
    }
    __syncthreads();

    int t = blockIdx.x * blockDim.x + threadIdx.x;   // 32*256*256 threads exact
    int px = t & 255;
    int py = (t >> 8) & 255;
    int b  = t >> 16;

    int gy0 = 2 * py - 1;
    int gx0 = 2 * px - 1;
    bool interior = (px - 1u < 254u) && (py - 1u < 254u);

    unsigned long long acc_t[8], acc_b[8];
    #pragma unroll
    for (int o = 0; o < 8; o++) { acc_t[o] = 0ull; acc_b[o] = 0ull; }

    #pragma unroll
    for (int c = 0; c < 3; c++) {
        float p[4][4];
        const float* xc = x + ((size_t)b * 3 + c) * 512 * 512;
        if (interior) {
            #pragma unroll
            for (int r = 0; r < 4; r++)
                #pragma unroll
                for (int cc = 0; cc < 4; cc++)
                    p[r][cc] = __ldg(xc + (gy0 + r) * 512 + (gx0 + cc));
        } else {
            #pragma unroll
            for (int r = 0; r < 4; r++) {
                int gy = gy0 + r;
                bool rok = (unsigned)gy < 512u;
                #pragma unroll
                for (int cc = 0; cc < 4; cc++) {
                    int gx = gx0 + cc;
                    bool ok = rok && ((unsigned)gx < 512u);
                    p[r][cc] = ok ? __ldg(xc + gy * 512 + gx) : 1.0f;
                }
            }
        }

        // packed pairs: pr[r][kx] = (p[r][kx], p[r][kx+1])
        unsigned long long pr[4][3];
        #pragma unroll
        for (int r = 0; r < 4; r++) {
            pr[r][0] = pk2(p[r][0], p[r][1]);
            pr[r][1] = pk2(p[r][1], p[r][2]);
            pr[r][2] = pk2(p[r][2], p[r][3]);
        }

        #pragma unroll
        for (int ky = 0; ky < 3; ky++)
            #pragma unroll
            for (int kx = 0; kx < 3; kx++)
                #pragma unroll
                for (int o = 0; o < 8; o++) {
                    unsigned long long w2 = *(const unsigned long long*)
                        &swd[2 * (((o * 3 + c) * 3 + ky) * 3 + kx)];
                    acc_t[o] = ffma2(pr[ky][kx],     w2, acc_t[o]);
                    acc_b[o] = ffma2(pr[ky + 1][kx], w2, acc_b[o]);
                }
    }

    int s[8];
    #pragma unroll
    for (int o = 0; o < 8; o++) {
        float f0, f1, f2, f3;
        upk2(acc_t[o], f0, f1);
        upk2(acc_b[o], f2, f3);
        float m = fmaxf(fmaxf(f0, f1), fmaxf(f2, f3));
        s[o] = sgnf(m);
    }
    uint2 out;
    out.x = (unsigned)pack4(s[0], s[1], s[2], s[3]);
    out.y = (unsigned)pack4(s[4], s[5], s[6], s[7]);
    g_s1[((size_t)b * 256 + py) * 256 + px] = out;
}

// ---------------------------------------------------------------------------
// Layer 2: ternary conv (8->16). Block = (b, 4-row group, og of 8 oc). (R9)
// ---------------------------------------------------------------------------
__global__ __launch_bounds__(256)
void l2_kernel() {
    __shared__ int sw[144];                          // this og's 72 int2
    int blk = blockIdx.x;
    int og  = blk & 1;
    int yg  = (blk >> 1) & 63;
    int b   = blk >> 7;
    for (int i = threadIdx.x; i < 144; i += blockDim.x) sw[i] = g_w2p[og * 144 + i];
    __syncthreads();
    const int2* sw2 = (const int2*)sw;               // [o*9 + pos], o in 0..7

    int x = threadIdx.x;
    if (x >= 254) return;
    int y0 = yg * 4;                                 // outputs y0..y0+3 (<254)

    int acc[4][8];
    #pragma unroll
    for (int p = 0; p < 4; p++)
        #pragma unroll
        for (int o = 0; o < 8; o++) acc[p][o] = 0;

    #pragma unroll
    for (int cc = 0; cc < 3; cc++) {
        uint2 d[6];                                  // input rows y0..y0+5 (clamped)
        #pragma unroll
        for (int r = 0; r < 6; r++) {
            int yi = y0 + r; if (yi > 255) yi = 255;
            d[r] = g_s1[((size_t)b * 256 + yi) * 256 + (x + cc)];
        }
        #pragma unroll
        for (int ky = 0; ky < 3; ky++)
            #pragma unroll
            for (int o = 0; o < 8; o++) {
                int2 w = sw2[o * 9 + ky * 3 + cc];
                #pragma unroll
                for (int p = 0; p < 4; p++) {
                    acc[p][o] = __dp4a((int)d[ky + p].x, w.x, acc[p][o]);
                    acc[p][o] = __dp4a((int)d[ky + p].y, w.y, acc[p][o]);
                }
            }
    }

    uint2* s2h = (uint2*)g_s2;                       // pixel = 2 uint2 halves
    #pragma unroll
    for (int p = 0; p < 4; p++) {
        if (y0 + p < 254) {
            uint2 v;
            v.x = (unsigned)pack4(sgni(acc[p][0]), sgni(acc[p][1]),
                                  sgni(acc[p][2]), sgni(acc[p][3]));
            v.y = (unsigned)pack4(sgni(acc[p][4]), sgni(acc[p][5]),
                                  sgni(acc[p][6]), sgni(acc[p][7]));
            s2h[(((size_t)b * 254 + (y0 + p)) * 254 + x) * 2 + og] = v;
        }
    }
}

// ---------------------------------------------------------------------------
// Layer 3: ternary conv (16->32). Block = (b, 2-row group, og of 8 oc). (R9)
// ---------------------------------------------------------------------------
__global__ __launch_bounds__(256)
void l3_kernel() {
    __shared__ int sw[288];                          // weights for this og only
    int blk = blockIdx.x;
    int og  = blk & 3;
    int yg  = (blk >> 2) % 126;
    int b   = blk / 504;                             // 504 = 126*4 blocks per b
    for (int i = threadIdx.x; i < 288; i += blockDim.x) sw[i] = g_w3p[og * 288 + i];
    __syncthreads();
    const int4* sw4 = (const int4*)sw;               // [o*9 + pos], o in 0..7

    int x = threadIdx.x;
    if (x >= 252) return;
    int y0 = yg * 2;

    int acc[2][8];
    #pragma unroll
    for (int p = 0; p < 2; p++)
        #pragma unroll
        for (int o = 0; o < 8; o++) acc[p][o] = 0;

    #pragma unroll
    for (int cc = 0; cc < 3; cc++) {
        int4 d[4];                                   // rows y0..y0+3 at col x+cc
        #pragma unroll
        for (int r = 0; r < 4; r++)
            d[r] = g_s2[((size_t)b * 254 + (y0 + r)) * 254 + (x + cc)];
        #pragma unroll
        for (int ky = 0; ky < 3; ky++)
            #pragma unroll
            for (int o = 0; o < 8; o++) {
                int4 w = sw4[o * 9 + ky * 3 + cc];
                #pragma unroll
                for (int p = 0; p < 2; p++) {
                    acc[p][o] = __dp4a(d[ky + p].x, w.x, acc[p][o]);
                    acc[p][o] = __dp4a(d[ky + p].y, w.y, acc[p][o]);
                    acc[p][o] = __dp4a(d[ky + p].z, w.z, acc[p][o]);
                    acc[p][o] = __dp4a(d[ky + p].w, w.w, acc[p][o]);
                }
            }
    }

    #pragma unroll
    for (int p = 0; p < 2; p++) {
        size_t pix = ((size_t)b * 252 + (y0 + p)) * 252 + x;
        uint2 v;
        v.x = (unsigned)pack4(sgni(acc[p][0]), sgni(acc[p][1]),
                              sgni(acc[p][2]), sgni(acc[p][3]));
        v.y = (unsigned)pack4(sgni(acc[p][4]), sgni(acc[p][5]),
                              sgni(acc[p][6]), sgni(acc[p][7]));
        g_s3v[og][pix] = v;                          // channels og*8 .. og*8+7
    }
}

// ---------------------------------------------------------------------------
// Layer 4: ternary conv (32->2) + hardtanh -> fp32 out. Block = (b, 4-row
// group). (R9)
// ---------------------------------------------------------------------------
__global__ __launch_bounds__(256)
void l4_kernel(float* __restrict__ out) {
    __shared__ int sw[144];
    for (int i = threadIdx.x; i < 144; i += blockDim.x) sw[i] = g_w4p[i];
    __syncthreads();
    const int4* sw4 = (const int4*)sw;               // [(o*9+pos)*2 + half]

    int b  = blockIdx.x / 63;
    int yg = blockIdx.x % 63;
    int x  = threadIdx.x;
    if (x >= 250) return;
    int y0 = yg * 4;                                 // outputs y0..y0+3 (<250)

    int acc[4][2];
    #pragma unroll
    for (int p = 0; p < 4; p++) { acc[p][0] = 0; acc[p][1] = 0; }

    #pragma unroll
    for (int cc = 0; cc < 3; cc++) {
        uint2 d[6][4];                               // rows y0..y0+5, 4 planes
        #pragma unroll
        for (int r = 0; r < 6; r++) {
            int yi = y0 + r; if (yi > 251) yi = 251;
            size_t pix = ((size_t)b * 252 + yi) * 252 + (x + cc);
            #pragma unroll
            for (int q = 0; q < 4; q++) d[r][q] = g_s3v[q][pix];
        }
        #pragma unroll
        for (int ky = 0; ky < 3; ky++)
            #pragma unroll
            for (int o = 0; o < 2; o++) {
                int4 wa = sw4[(o * 9 + ky * 3 + cc) * 2 + 0];
                int4 wb = sw4[(o * 9 + ky * 3 + cc) * 2 + 1];
                #pragma unroll
                for (int p = 0; p < 4; p++) {
                    const uint2* dr = d[ky + p];
                    acc[p][o] = __dp4a((int)dr[0].x, wa.x, acc[p][o]);
                    acc[p][o] = __dp4a((int)dr[0].y, wa.y, acc[p][o]);
                    acc[p][o] = __dp4a((int)dr[1].x, wa.z, acc[p][o]);
                    acc[p][o] = __dp4a((int)dr[1].y, wa.w, acc[p][o]);
                    acc[p][o] = __dp4a((int)dr[2].x, wb.x, acc[p][o]);
                    acc[p][o] = __dp4a((int)dr[2].y, wb.y, acc[p][o]);
                    acc[p][o] = __dp4a((int)dr[3].x, wb.z, acc[p][o]);
                    acc[p][o] = __dp4a((int)dr[3].y, wb.w, acc[p][o]);
                }
            }
    }

    #pragma unroll
    for (int p = 0; p < 4; p++) {
        if (y0 + p < 250) {
            #pragma unroll
            for (int o = 0; o < 2; o++) {
                float v = fminf(fmaxf((float)acc[p][o], -1.f), 1.f);
                out[(size_t)b * 125000 + (size_t)o * 62500 + (size_t)(y0 + p) * 250 + x] = v;
            }
        }
    }
}

// ---------------------------------------------------------------------------
extern "C" void kernel_launch(void* const* d_in, const int* in_sizes, int n_in,
                              void* d_out, int out_size) {
    const float* x  = (const float*)d_in[0];
    const float* w1 = (const float*)d_in[1];
    const float* w2 = (const float*)d_in[2];
    const float* w3 = (const float*)d_in[3];
    const float* w4 = (const float*)d_in[4];
    float* out = (float*)d_out;

    prep_kernel<<<1, 256>>>(w1, w2, w3, w4);
    l1_kernel<<<8192, 256>>>(x);                    // 32*256*256 threads
    l2_kernel<<<32 * 64 * 2, 256>>>();              // block = (b, 4 rows, og)
    l3_kernel<<<32 * 126 * 4, 256>>>();             // block = (b, 2 rows, og)
    l4_kernel<<<32 * 63, 256>>>(out);               // block = (b, 4 rows)
}

// round 11
// speedup vs baseline: 1.4064x; 1.4064x over previous
#include <cuda_runtime.h>
#include <cstdint>

// ---------------------------------------------------------------------------
// MCNET binarized CNN (algebraic identities, see R0):
//   * sign(maxpool(hardtanh(v))) == sign(max(v))
//   * sign(hardtanh(int n)) == sign(n)
//   * L2..L4 activations are ternary {-1,0,+1} int8 sign maps
// R11: l1/l2/l4 = R9 exact. l3 rewritten on int8 tensor cores:
// per output row, A = im2col [16px x 144] s8 via ldmatrix from a staged
// 3-row smem tile; B = sign weights prepacked (in prep_kernel) into the
// mma.m16n8k32/.k16 per-lane fragment layout; D = s32, sign-packed to the
// same uint2 planes l4 consumes.
// ---------------------------------------------------------------------------

static __device__ uint2 g_s1[32u * 256 * 256];         // [b,y,x, 8ch]  16.8 MB
static __device__ int4  g_s2[32u * 254 * 254];         // [b,y,x,16ch]  33.0 MB
static __device__ uint2 g_s3v[4][32u * 252 * 252];     // [plane][b,y,x] 8ch each

static __device__ float g_w1f[216];    // [o=8][c=3][ky][kx] as float +-1/0
static __device__ int   g_w2p[288];    // [o=16][9 pos][2 packs of 4ch]
static __device__ uint2 g_w3frag[640]; // [(nt*5+chunk)*32 + lane] = {b0,b1} mma frags
static __device__ int   g_w4p[144];    // [o=2 ][9 pos][8 packs of 4ch]

__device__ __forceinline__ int sgnf(float v) { return (v > 0.f) - (v < 0.f); }
__device__ __forceinline__ int sgni(int v)   { return (v > 0) - (v < 0); }
__device__ __forceinline__ int pack4(int a, int b, int c, int d) {
    return (a & 0xFF) | ((b & 0xFF) << 8) | ((c & 0xFF) << 16) | ((d & 0xFF) << 24);
}

// ---- mma helpers ----------------------------------------------------------
__device__ __forceinline__ unsigned smem_u32(const void* p) {
    return (unsigned)__cvta_generic_to_shared(p);
}
__device__ __forceinline__ void ldmatrix_x4(unsigned& a0, unsigned& a1,
                                            unsigned& a2, unsigned& a3, unsigned addr) {
    asm volatile("ldmatrix.sync.aligned.m8n8.x4.shared.b16 {%0,%1,%2,%3}, [%4];"
                 : "=r"(a0), "=r"(a1), "=r"(a2), "=r"(a3) : "r"(addr));
}
__device__ __forceinline__ void ldmatrix_x2(unsigned& a0, unsigned& a1, unsigned addr) {
    asm volatile("ldmatrix.sync.aligned.m8n8.x2.shared.b16 {%0,%1}, [%2];"
                 : "=r"(a0), "=r"(a1) : "r"(addr));
}
__device__ __forceinline__ void mma_k32(int* c, unsigned a0, unsigned a1,
                                        unsigned a2, unsigned a3,
                                        unsigned b0, unsigned b1) {
    asm volatile("mma.sync.aligned.m16n8k32.row.col.s32.s8.s8.s32 "
                 "{%0,%1,%2,%3},{%4,%5,%6,%7},{%8,%9},{%0,%1,%2,%3};"
                 : "+r"(c[0]), "+r"(c[1]), "+r"(c[2]), "+r"(c[3])
                 : "r"(a0), "r"(a1), "r"(a2), "r"(a3), "r"(b0), "r"(b1));
}
__device__ __forceinline__ void mma_k16(int* c, unsigned a0, unsigned a1, unsigned b0) {
    asm volatile("mma.sync.aligned.m16n8k16.row.col.s32.s8.s8.s32 "
                 "{%0,%1,%2,%3},{%4,%5},{%6},{%0,%1,%2,%3};"
                 : "+r"(c[0]), "+r"(c[1]), "+r"(c[2]), "+r"(c[3])
                 : "r"(a0), "r"(a1), "r"(b0));
}

// ---------------------------------------------------------------------------
__global__ void prep_kernel(const float* __restrict__ w1, const float* __restrict__ w2,
                            const float* __restrict__ w3, const float* __restrict__ w4) {
    int t = threadIdx.x;
    for (int i = t; i < 216; i += blockDim.x) g_w1f[i] = (float)sgnf(w1[i]);
    for (int i = t; i < 288; i += blockDim.x) {
        int h = i & 1, pos = (i >> 1) % 9, o = i / 18;
        int ky = pos / 3, kx = pos % 3;
        int s[4];
        #pragma unroll
        for (int j = 0; j < 4; j++)
            s[j] = sgnf(w2[((o * 8 + (4 * h + j)) * 3 + ky) * 3 + kx]);
        g_w2p[i] = pack4(s[0], s[1], s[2], s[3]);
    }
    // w3 -> mma B fragments. B is col-major [K x 8oc] per n-tile; lane layout:
    //   b0 byte j = w[oc = nt*8 + lane/4][ch = (lane%4)*4 + j][tap 2*chunk]
    //   b1 byte j = same, tap 2*chunk+1   (chunk 4: b0 = tap 8, b1 = 0)
    for (int i = t; i < 640; i += blockDim.x) {
        int lane = i & 31, nc = i >> 5;
        int nt = nc / 5, c = nc % 5;
        int oc = nt * 8 + (lane >> 2);
        int chb = (lane & 3) * 4;
        int tapA = (c < 4) ? 2 * c : 8;
        int sA[4];
        #pragma unroll
        for (int j = 0; j < 4; j++)
            sA[j] = sgnf(w3[((oc * 16 + chb + j) * 3 + tapA / 3) * 3 + tapA % 3]);
        unsigned b0 = (unsigned)pack4(sA[0], sA[1], sA[2], sA[3]);
        unsigned b1 = 0;
        if (c < 4) {
            int tapB = 2 * c + 1;
            int sB[4];
            #pragma unroll
            for (int j = 0; j < 4; j++)
                sB[j] = sgnf(w3[((oc * 16 + chb + j) * 3 + tapB / 3) * 3 + tapB % 3]);
            b1 = (unsigned)pack4(sB[0], sB[1], sB[2], sB[3]);
        }
        g_w3frag[i] = make_uint2(b0, b1);
    }
    for (int i = t; i < 144; i += blockDim.x) {
        int q = i & 7, pos = (i >> 3) % 9, o = i / 72;
        int ky = pos / 3, kx = pos % 3;
        int s[4];
        #pragma unroll
        for (int j = 0; j < 4; j++)
            s[j] = sgnf(w4[((o * 32 + (4 * q + j)) * 3 + ky) * 3 + kx]);
        g_w4p[i] = pack4(s[0], s[1], s[2], s[3]);
    }
}

// ---------------------------------------------------------------------------
// Layer 1: fp conv (3->8), pad 1.0, fused hardtanh+maxpool+sign. (R9 exact)
// ---------------------------------------------------------------------------
__global__ __launch_bounds__(256)
void l1_kernel(const float* __restrict__ x) {
    __shared__ float sw[216];
    for (int i = threadIdx.x; i < 216; i += blockDim.x) sw[i] = g_w1f[i];
    __syncthreads();

    int t = blockIdx.x * blockDim.x + threadIdx.x;   // 32*256*256 threads exact
    int px = t & 255;
    int py = (t >> 8) & 255;
    int b  = t >> 16;

    float acc[4][8];
    #pragma unroll
    for (int p = 0; p < 4; p++)
        #pragma unroll
        for (int o = 0; o < 8; o++) acc[p][o] = 0.f;

    int gy0 = 2 * py - 1;
    int gx0 = 2 * px - 1;

    #pragma unroll
    for (int c = 0; c < 3; c++) {
        float p[4][4];
        const float* xc = x + ((size_t)b * 3 + c) * 512 * 512;
        #pragma unroll
        for (int r = 0; r < 4; r++) {
            int gy = gy0 + r;
            bool rok = (unsigned)gy < 512u;
            #pragma unroll
            for (int cc = 0; cc < 4; cc++) {
                int gx = gx0 + cc;
                bool ok = rok && ((unsigned)gx < 512u);
                p[r][cc] = ok ? __ldg(xc + gy * 512 + gx) : 1.0f;
            }
        }
        #pragma unroll
        for (int ky = 0; ky < 3; ky++)
            #pragma unroll
            for (int kx = 0; kx < 3; kx++)
                #pragma unroll
                for (int o = 0; o < 8; o++) {
                    float w = sw[((o * 3 + c) * 3 + ky) * 3 + kx];
                    #pragma unroll
                    for (int dy = 0; dy < 2; dy++)
                        #pragma unroll
                        for (int dx = 0; dx < 2; dx++)
                            acc[dy * 2 + dx][o] = fmaf(p[ky + dy][kx + dx], w,
                                                       acc[dy * 2 + dx][o]);
                }
    }

    int s[8];
    #pragma unroll
    for (int o = 0; o < 8; o++) {
        float m = fmaxf(fmaxf(acc[0][o], acc[1][o]), fmaxf(acc[2][o], acc[3][o]));
        s[o] = sgnf(m);
    }
    uint2 out;
    out.x = (unsigned)pack4(s[0], s[1], s[2], s[3]);
    out.y = (unsigned)pack4(s[4], s[5], s[6], s[7]);
    g_s1[((size_t)b * 256 + py) * 256 + px] = out;
}

// ---------------------------------------------------------------------------
// Layer 2: ternary conv (8->16). Block = (b, 4-row group, og of 8 oc). (R9)
// ---------------------------------------------------------------------------
__global__ __launch_bounds__(256)
void l2_kernel() {
    __shared__ int sw[144];                          // this og's 72 int2
    int blk = blockIdx.x;
    int og  = blk & 1;
    int yg  = (blk >> 1) & 63;
    int b   = blk >> 7;
    for (int i = threadIdx.x; i < 144; i += blockDim.x) sw[i] = g_w2p[og * 144 + i];
    __syncthreads();
    const int2* sw2 = (const int2*)sw;               // [o*9 + pos], o in 0..7

    int x = threadIdx.x;
    if (x >= 254) return;
    int y0 = yg * 4;                                 // outputs y0..y0+3 (<254)

    int acc[4][8];
    #pragma unroll
    for (int p = 0; p < 4; p++)
        #pragma unroll
        for (int o = 0; o < 8; o++) acc[p][o] = 0;

    #pragma unroll
    for (int cc = 0; cc < 3; cc++) {
        uint2 d[6];                                  // input rows y0..y0+5 (clamped)
        #pragma unroll
        for (int r = 0; r < 6; r++) {
            int yi = y0 + r; if (yi > 255) yi = 255;
            d[r] = g_s1[((size_t)b * 256 + yi) * 256 + (x + cc)];
        }
        #pragma unroll
        for (int ky = 0; ky < 3; ky++)
            #pragma unroll
            for (int o = 0; o < 8; o++) {
                int2 w = sw2[o * 9 + ky * 3 + cc];
                #pragma unroll
                for (int p = 0; p < 4; p++) {
                    acc[p][o] = __dp4a((int)d[ky + p].x, w.x, acc[p][o]);
                    acc[p][o] = __dp4a((int)d[ky + p].y, w.y, acc[p][o]);
                }
            }
    }

    uint2* s2h = (uint2*)g_s2;                       // pixel = 2 uint2 halves
    #pragma unroll
    for (int p = 0; p < 4; p++) {
        if (y0 + p < 254) {
            uint2 v;
            v.x = (unsigned)pack4(sgni(acc[p][0]), sgni(acc[p][1]),
                                  sgni(acc[p][2]), sgni(acc[p][3]));
            v.y = (unsigned)pack4(sgni(acc[p][4]), sgni(acc[p][5]),
                                  sgni(acc[p][6]), sgni(acc[p][7]));
            s2h[(((size_t)b * 254 + (y0 + p)) * 254 + x) * 2 + og] = v;
        }
    }
}

// ---------------------------------------------------------------------------
// Layer 3: ternary conv (16->32) on int8 tensor cores.
// Block = (b, output row y). Stages s2 rows y..y+2 (254 x 16B each) in smem.
// Warp-tile = 16 x-pixels x 32 oc: A via ldmatrix (rows = pixel vectors),
// B from prepacked g_w3frag, 4x mma.k32 (taps 0-7 in pairs) + 1x mma.k16
// (tap 8) per 8-oc n-tile. Epilogue: sign, per-warp smem transpose, store
// uint2 planes (same format as R9).
// ---------------------------------------------------------------------------
__global__ __launch_bounds__(256)
void l3_kernel() {
    __shared__ __align__(16) uint4 sraw[3][256];               // 16B pixel vecs
    __shared__ __align__(16) unsigned short sepi[8][16][16];   // per-warp stage

    int blk = blockIdx.x;
    int y = blk % 252;
    int b = blk / 252;

    const uint4* src = (const uint4*)g_s2;
    for (int i = threadIdx.x; i < 3 * 254; i += 256) {
        int r = i / 254, cx = i % 254;
        sraw[r][cx] = src[((size_t)b * 254 + (y + r)) * 254 + cx];
    }
    __syncthreads();

    int lane = threadIdx.x & 31;
    int w    = threadIdx.x >> 5;

    // B fragments: nc = nt*5 + chunk
    uint2 bf[20];
    #pragma unroll
    for (int nc = 0; nc < 20; nc++) bf[nc] = g_w3frag[nc * 32 + lane];

    int grp = lane >> 3, li = lane & 7;

    for (int t = w; t < 16; t += 8) {
        int x0 = t * 16;

        int c_[4][4];
        #pragma unroll
        for (int nt = 0; nt < 4; nt++)
            #pragma unroll
            for (int j = 0; j < 4; j++) c_[nt][j] = 0;

        // chunks 0..3: taps (2c, 2c+1), A tiles: g0 px0-7 tapA, g1 px8-15 tapA,
        //                                        g2 px0-7 tapB, g3 px8-15 tapB
        #pragma unroll
        for (int c = 0; c < 4; c++) {
            int tap = 2 * c + (grp >> 1);
            int ky = tap / 3, kx = tap % 3;
            int col = x0 + ((grp & 1) << 3) + li + kx;
            if (col > 253) col = 253;
            unsigned a0, a1, a2, a3;
            ldmatrix_x4(a0, a1, a2, a3, smem_u32(&sraw[ky][col]));
            #pragma unroll
            for (int nt = 0; nt < 4; nt++)
                mma_k32(c_[nt], a0, a1, a2, a3,
                        bf[nt * 5 + c].x, bf[nt * 5 + c].y);
        }
        // chunk 4: tap 8 only, K=16
        {
            int col = x0 + ((grp & 1) << 3) + li + 2;    // ky=2, kx=2
            if (col > 253) col = 253;
            unsigned a0, a1;
            ldmatrix_x2(a0, a1, smem_u32(&sraw[2][col]));
            #pragma unroll
            for (int nt = 0; nt < 4; nt++)
                mma_k16(c_[nt], a0, a1, bf[nt * 5 + 4].x);
        }

        // epilogue: lane owns rows (lane/4, lane/4+8), oc cols 2*(lane%4)+{0,1}
        int q = lane & 3;
        int r = lane >> 2;
        #pragma unroll
        for (int nt = 0; nt < 4; nt++) {
            unsigned lo = (unsigned)(sgni(c_[nt][0]) & 0xFF) |
                          ((unsigned)(sgni(c_[nt][1]) & 0xFF) << 8);
            unsigned hi = (unsigned)(sgni(c_[nt][2]) & 0xFF) |
                          ((unsigned)(sgni(c_[nt][3]) & 0xFF) << 8);
            sepi[w][r][nt * 4 + q]     = (unsigned short)lo;
            sepi[w][r + 8][nt * 4 + q] = (unsigned short)hi;
        }
        __syncwarp();

        int px = lane & 15;
        int gx = x0 + px;
        if (gx < 252) {
            const unsigned* row32 = (const unsigned*)sepi[w][px];
            #pragma unroll
            for (int h = 0; h < 2; h++) {
                int og = (lane >> 4) + h * 2;
                uint2 v;
                v.x = row32[og * 2];
                v.y = row32[og * 2 + 1];
                g_s3v[og][((size_t)b * 252 + y) * 252 + gx] = v;
            }
        }
        __syncwarp();
    }
}

// ---------------------------------------------------------------------------
// Layer 4: ternary conv (32->2) + hardtanh -> fp32 out. Block = (b, 4-row
// group). (R9)
// ---------------------------------------------------------------------------
__global__ __launch_bounds__(256)
void l4_kernel(float* __restrict__ out) {
    __shared__ int sw[144];
    for (int i = threadIdx.x; i < 144; i += blockDim.x) sw[i] = g_w4p[i];
    __syncthreads();
    const int4* sw4 = (const int4*)sw;               // [(o*9+pos)*2 + half]

    int b  = blockIdx.x / 63;
    int yg = blockIdx.x % 63;
    int x  = threadIdx.x;
    if (x >= 250) return;
    int y0 = yg * 4;                                 // outputs y0..y0+3 (<250)

    int acc[4][2];
    #pragma unroll
    for (int p = 0; p < 4; p++) { acc[p][0] = 0; acc[p][1] = 0; }

    #pragma unroll
    for (int cc = 0; cc < 3; cc++) {
        uint2 d[6][4];                               // rows y0..y0+5, 4 planes
        #pragma unroll
        for (int r = 0; r < 6; r++) {
            int yi = y0 + r; if (yi > 251) yi = 251;
            size_t pix = ((size_t)b * 252 + yi) * 252 + (x + cc);
            #pragma unroll
            for (int q = 0; q < 4; q++) d[r][q] = g_s3v[q][pix];
        }
        #pragma unroll
        for (int ky = 0; ky < 3; ky++)
            #pragma unroll
            for (int o = 0; o < 2; o++) {
                int4 wa = sw4[(o * 9 + ky * 3 + cc) * 2 + 0];
                int4 wb = sw4[(o * 9 + ky * 3 + cc) * 2 + 1];
                #pragma unroll
                for (int p = 0; p < 4; p++) {
                    const uint2* dr = d[ky + p];
                    acc[p][o] = __dp4a((int)dr[0].x, wa.x, acc[p][o]);
                    acc[p][o] = __dp4a((int)dr[0].y, wa.y, acc[p][o]);
                    acc[p][o] = __dp4a((int)dr[1].x, wa.z, acc[p][o]);
                    acc[p][o] = __dp4a((int)dr[1].y, wa.w, acc[p][o]);
                    acc[p][o] = __dp4a((int)dr[2].x, wb.x, acc[p][o]);
                    acc[p][o] = __dp4a((int)dr[2].y, wb.y, acc[p][o]);
                    acc[p][o] = __dp4a((int)dr[3].x, wb.z, acc[p][o]);
                    acc[p][o] = __dp4a((int)dr[3].y, wb.w, acc[p][o]);
                }
            }
    }

    #pragma unroll
    for (int p = 0; p < 4; p++) {
        if (y0 + p < 250) {
            #pragma unroll
            for (int o = 0; o < 2; o++) {
                float v = fminf(fmaxf((float)acc[p][o], -1.f), 1.f);
                out[(size_t)b * 125000 + (size_t)o * 62500 + (size_t)(y0 + p) * 250 + x] = v;
            }
        }
    }
}

// ---------------------------------------------------------------------------
extern "C" void kernel_launch(void* const* d_in, const int* in_sizes, int n_in,
                              void* d_out, int out_size) {
    const float* x  = (const float*)d_in[0];
    const float* w1 = (const float*)d_in[1];
    const float* w2 = (const float*)d_in[2];
    const float* w3 = (const float*)d_in[3];
    const float* w4 = (const float*)d_in[4];
    float* out = (float*)d_out;

    prep_kernel<<<1, 256>>>(w1, w2, w3, w4);
    l1_kernel<<<8192, 256>>>(x);                    // 32*256*256 threads
    l2_kernel<<<32 * 64 * 2, 256>>>();              // block = (b, 4 rows, og)
    l3_kernel<<<32 * 252, 256>>>();                 // block = (b, output row)
    l4_kernel<<<32 * 63, 256>>>(out);               // block = (b, 4 rows)
}

// round 12
// speedup vs baseline: 1.4662x; 1.0425x over previous
#include <cuda_runtime.h>
#include <cstdint>

// ---------------------------------------------------------------------------
// MCNET binarized CNN (algebraic identities, see R0):
//   * sign(maxpool(hardtanh(v))) == sign(max(v))
//   * sign(hardtanh(int n)) == sign(n)
//   * L2..L4 activations are ternary {-1,0,+1} int8 sign maps
// R12: l2/l4 frozen (R9). l3 (s8 mma): A-fragments persistent, B streamed
// from global per n-tile -> regs ~50, 5 blocks/SM. l1: weights reordered
// [c][ky][kx][o] for LDS.128 (216 LDS.32 -> 54 LDS.128) + interior fast path.
// ---------------------------------------------------------------------------

static __device__ uint2 g_s1[32u * 256 * 256];         // [b,y,x, 8ch]  16.8 MB
static __device__ int4  g_s2[32u * 254 * 254];         // [b,y,x,16ch]  33.0 MB
static __device__ uint2 g_s3v[4][32u * 252 * 252];     // [plane][b,y,x] 8ch each

static __device__ float g_w1f[216];    // [o=8][c=3][ky][kx] as float +-1/0
static __device__ int   g_w2p[288];    // [o=16][9 pos][2 packs of 4ch]
static __device__ uint2 g_w3frag[640]; // [(nt*5+chunk)*32 + lane] = {b0,b1} mma frags
static __device__ int   g_w4p[144];    // [o=2 ][9 pos][8 packs of 4ch]

__device__ __forceinline__ int sgnf(float v) { return (v > 0.f) - (v < 0.f); }
__device__ __forceinline__ int sgni(int v)   { return (v > 0) - (v < 0); }
__device__ __forceinline__ int pack4(int a, int b, int c, int d) {
    return (a & 0xFF) | ((b & 0xFF) << 8) | ((c & 0xFF) << 16) | ((d & 0xFF) << 24);
}

// ---- mma helpers ----------------------------------------------------------
__device__ __forceinline__ unsigned smem_u32(const void* p) {
    return (unsigned)__cvta_generic_to_shared(p);
}
__device__ __forceinline__ void ldmatrix_x4(unsigned& a0, unsigned& a1,
                                            unsigned& a2, unsigned& a3, unsigned addr) {
    asm volatile("ldmatrix.sync.aligned.m8n8.x4.shared.b16 {%0,%1,%2,%3}, [%4];"
                 : "=r"(a0), "=r"(a1), "=r"(a2), "=r"(a3) : "r"(addr));
}
__device__ __forceinline__ void ldmatrix_x2(unsigned& a0, unsigned& a1, unsigned addr) {
    asm volatile("ldmatrix.sync.aligned.m8n8.x2.shared.b16 {%0,%1}, [%2];"
                 : "=r"(a0), "=r"(a1) : "r"(addr));
}
__device__ __forceinline__ void mma_k32(int* c, unsigned a0, unsigned a1,
                                        unsigned a2, unsigned a3,
                                        unsigned b0, unsigned b1) {
    asm volatile("mma.sync.aligned.m16n8k32.row.col.s32.s8.s8.s32 "
                 "{%0,%1,%2,%3},{%4,%5,%6,%7},{%8,%9},{%0,%1,%2,%3};"
                 : "+r"(c[0]), "+r"(c[1]), "+r"(c[2]), "+r"(c[3])
                 : "r"(a0), "r"(a1), "r"(a2), "r"(a3), "r"(b0), "r"(b1));
}
__device__ __forceinline__ void mma_k16(int* c, unsigned a0, unsigned a1, unsigned b0) {
    asm volatile("mma.sync.aligned.m16n8k16.row.col.s32.s8.s8.s32 "
                 "{%0,%1,%2,%3},{%4,%5},{%6},{%0,%1,%2,%3};"
                 : "+r"(c[0]), "+r"(c[1]), "+r"(c[2]), "+r"(c[3])
                 : "r"(a0), "r"(a1), "r"(b0));
}

// ---------------------------------------------------------------------------
__global__ void prep_kernel(const float* __restrict__ w1, const float* __restrict__ w2,
                            const float* __restrict__ w3, const float* __restrict__ w4) {
    int t = threadIdx.x;
    for (int i = t; i < 216; i += blockDim.x) g_w1f[i] = (float)sgnf(w1[i]);
    for (int i = t; i < 288; i += blockDim.x) {
        int h = i & 1, pos = (i >> 1) % 9, o = i / 18;
        int ky = pos / 3, kx = pos % 3;
        int s[4];
        #pragma unroll
        for (int j = 0; j < 4; j++)
            s[j] = sgnf(w2[((o * 8 + (4 * h + j)) * 3 + ky) * 3 + kx]);
        g_w2p[i] = pack4(s[0], s[1], s[2], s[3]);
    }
    // w3 -> mma B fragments (layout as R11)
    for (int i = t; i < 640; i += blockDim.x) {
        int lane = i & 31, nc = i >> 5;
        int nt = nc / 5, c = nc % 5;
        int oc = nt * 8 + (lane >> 2);
        int chb = (lane & 3) * 4;
        int tapA = (c < 4) ? 2 * c : 8;
        int sA[4];
        #pragma unroll
        for (int j = 0; j < 4; j++)
            sA[j] = sgnf(w3[((oc * 16 + chb + j) * 3 + tapA / 3) * 3 + tapA % 3]);
        unsigned b0 = (unsigned)pack4(sA[0], sA[1], sA[2], sA[3]);
        unsigned b1 = 0;
        if (c < 4) {
            int tapB = 2 * c + 1;
            int sB[4];
            #pragma unroll
            for (int j = 0; j < 4; j++)
                sB[j] = sgnf(w3[((oc * 16 + chb + j) * 3 + tapB / 3) * 3 + tapB % 3]);
            b1 = (unsigned)pack4(sB[0], sB[1], sB[2], sB[3]);
        }
        g_w3frag[i] = make_uint2(b0, b1);
    }
    for (int i = t; i < 144; i += blockDim.x) {
        int q = i & 7, pos = (i >> 3) % 9, o = i / 72;
        int ky = pos / 3, kx = pos % 3;
        int s[4];
        #pragma unroll
        for (int j = 0; j < 4; j++)
            s[j] = sgnf(w4[((o * 32 + (4 * q + j)) * 3 + ky) * 3 + kx]);
        g_w4p[i] = pack4(s[0], s[1], s[2], s[3]);
    }
}

// ---------------------------------------------------------------------------
// Layer 1: fp conv (3->8), pad 1.0, fused hardtanh+maxpool+sign.
// Weights reordered in smem to [c][ky][kx][o] -> 2x LDS.128 per tap.
// Interior threads (98.4%) take an unpredicated load path.
// ---------------------------------------------------------------------------
__global__ __launch_bounds__(256)
void l1_kernel(const float* __restrict__ x) {
    __shared__ __align__(16) float sw[216];          // [(c*9+ky*3+kx)*8 + o]
    for (int i = threadIdx.x; i < 216; i += 256) {
        int o = i & 7, rest = i >> 3;
        int kx = rest % 3, ky = (rest / 3) % 3, c = rest / 9;
        sw[i] = g_w1f[((o * 3 + c) * 3 + ky) * 3 + kx];
    }
    __syncthreads();
    const float4* sw4 = (const float4*)sw;           // [tap*2 + half]

    int t = blockIdx.x * blockDim.x + threadIdx.x;   // 32*256*256 threads exact
    int px = t & 255;
    int py = (t >> 8) & 255;
    int b  = t >> 16;

    float acc[4][8];
    #pragma unroll
    for (int p = 0; p < 4; p++)
        #pragma unroll
        for (int o = 0; o < 8; o++) acc[p][o] = 0.f;

    int gy0 = 2 * py - 1;
    int gx0 = 2 * px - 1;
    bool interior = (px - 1u < 254u) && (py - 1u < 254u);

    #pragma unroll
    for (int c = 0; c < 3; c++) {
        float p[4][4];
        const float* xc = x + ((size_t)b * 3 + c) * 512 * 512;
        if (interior) {
            #pragma unroll
            for (int r = 0; r < 4; r++)
                #pragma unroll
                for (int cc = 0; cc < 4; cc++)
                    p[r][cc] = __ldg(xc + (gy0 + r) * 512 + (gx0 + cc));
        } else {
            #pragma unroll
            for (int r = 0; r < 4; r++) {
                int gy = gy0 + r;
                bool rok = (unsigned)gy < 512u;
                #pragma unroll
                for (int cc = 0; cc < 4; cc++) {
                    int gx = gx0 + cc;
                    bool ok = rok && ((unsigned)gx < 512u);
                    p[r][cc] = ok ? __ldg(xc + gy * 512 + gx) : 1.0f;
                }
            }
        }
        #pragma unroll
        for (int ky = 0; ky < 3; ky++)
            #pragma unroll
            for (int kx = 0; kx < 3; kx++) {
                int tap = c * 9 + ky * 3 + kx;
                float4 wa = sw4[tap * 2 + 0];        // o = 0..3
                float4 wb = sw4[tap * 2 + 1];        // o = 4..7
                float wv[8] = {wa.x, wa.y, wa.z, wa.w, wb.x, wb.y, wb.z, wb.w};
                #pragma unroll
                for (int o = 0; o < 8; o++) {
                    float w = wv[o];
                    #pragma unroll
                    for (int dy = 0; dy < 2; dy++)
                        #pragma unroll
                        for (int dx = 0; dx < 2; dx++)
                            acc[dy * 2 + dx][o] = fmaf(p[ky + dy][kx + dx], w,
                                                       acc[dy * 2 + dx][o]);
                }
            }
    }

    int s[8];
    #pragma unroll
    for (int o = 0; o < 8; o++) {
        float m = fmaxf(fmaxf(acc[0][o], acc[1][o]), fmaxf(acc[2][o], acc[3][o]));
        s[o] = sgnf(m);
    }
    uint2 out;
    out.x = (unsigned)pack4(s[0], s[1], s[2], s[3]);
    out.y = (unsigned)pack4(s[4], s[5], s[6], s[7]);
    g_s1[((size_t)b * 256 + py) * 256 + px] = out;
}

// ---------------------------------------------------------------------------
// Layer 2: ternary conv (8->16). Block = (b, 4-row group, og of 8 oc). (R9)
// ---------------------------------------------------------------------------
__global__ __launch_bounds__(256)
void l2_kernel() {
    __shared__ int sw[144];                          // this og's 72 int2
    int blk = blockIdx.x;
    int og  = blk & 1;
    int yg  = (blk >> 1) & 63;
    int b   = blk >> 7;
    for (int i = threadIdx.x; i < 144; i += blockDim.x) sw[i] = g_w2p[og * 144 + i];
    __syncthreads();
    const int2* sw2 = (const int2*)sw;               // [o*9 + pos], o in 0..7

    int x = threadIdx.x;
    if (x >= 254) return;
    int y0 = yg * 4;                                 // outputs y0..y0+3 (<254)

    int acc[4][8];
    #pragma unroll
    for (int p = 0; p < 4; p++)
        #pragma unroll
        for (int o = 0; o < 8; o++) acc[p][o] = 0;

    #pragma unroll
    for (int cc = 0; cc < 3; cc++) {
        uint2 d[6];                                  // input rows y0..y0+5 (clamped)
        #pragma unroll
        for (int r = 0; r < 6; r++) {
            int yi = y0 + r; if (yi > 255) yi = 255;
            d[r] = g_s1[((size_t)b * 256 + yi) * 256 + (x + cc)];
        }
        #pragma unroll
        for (int ky = 0; ky < 3; ky++)
            #pragma unroll
            for (int o = 0; o < 8; o++) {
                int2 w = sw2[o * 9 + ky * 3 + cc];
                #pragma unroll
                for (int p = 0; p < 4; p++) {
                    acc[p][o] = __dp4a((int)d[ky + p].x, w.x, acc[p][o]);
                    acc[p][o] = __dp4a((int)d[ky + p].y, w.y, acc[p][o]);
                }
            }
    }

    uint2* s2h = (uint2*)g_s2;                       // pixel = 2 uint2 halves
    #pragma unroll
    for (int p = 0; p < 4; p++) {
        if (y0 + p < 254) {
            uint2 v;
            v.x = (unsigned)pack4(sgni(acc[p][0]), sgni(acc[p][1]),
                                  sgni(acc[p][2]), sgni(acc[p][3]));
            v.y = (unsigned)pack4(sgni(acc[p][4]), sgni(acc[p][5]),
                                  sgni(acc[p][6]), sgni(acc[p][7]));
            s2h[(((size_t)b * 254 + (y0 + p)) * 254 + x) * 2 + og] = v;
        }
    }
}

// ---------------------------------------------------------------------------
// Layer 3: ternary conv (16->32) on int8 tensor cores.
// R12: A fragments held persistent across the n-tile loop; B fragments
// streamed from global (L1-hot, coalesced). Per-nt accumulators + immediate
// epilogue -> ~50 regs -> 5 blocks/SM.
// ---------------------------------------------------------------------------
__global__ __launch_bounds__(256)
void l3_kernel() {
    __shared__ __align__(16) uint4 sraw[3][256];               // 16B pixel vecs
    __shared__ __align__(16) unsigned short sepi[8][16][16];   // per-warp stage

    int blk = blockIdx.x;
    int y = blk % 252;
    int b = blk / 252;

    const uint4* src = (const uint4*)g_s2;
    for (int i = threadIdx.x; i < 3 * 254; i += 256) {
        int r = i / 254, cx = i % 254;
        sraw[r][cx] = src[((size_t)b * 254 + (y + r)) * 254 + cx];
    }
    __syncthreads();

    int lane = threadIdx.x & 31;
    int w    = threadIdx.x >> 5;
    int grp = lane >> 3, li = lane & 7;

    for (int t = w; t < 16; t += 8) {
        int x0 = t * 16;

        // A fragments: chunks 0..3 (taps 2c,2c+1) and chunk 4 (tap 8)
        unsigned a[4][4];
        unsigned a40, a41;
        #pragma unroll
        for (int c = 0; c < 4; c++) {
            int tap = 2 * c + (grp >> 1);
            int ky = tap / 3, kx = tap % 3;
            int col = x0 + ((grp & 1) << 3) + li + kx;
            if (col > 253) col = 253;
            ldmatrix_x4(a[c][0], a[c][1], a[c][2], a[c][3],
                        smem_u32(&sraw[ky][col]));
        }
        {
            int col = x0 + ((grp & 1) << 3) + li + 2;    // ky=2, kx=2
            if (col > 253) col = 253;
            ldmatrix_x2(a40, a41, smem_u32(&sraw[2][col]));
        }

        // n-tile loop: B streamed from global, 4 accs, immediate epilogue
        int q = lane & 3;
        int r = lane >> 2;
        #pragma unroll
        for (int nt = 0; nt < 4; nt++) {
            int acc[4] = {0, 0, 0, 0};
            #pragma unroll
            for (int c = 0; c < 4; c++) {
                uint2 bf = g_w3frag[(nt * 5 + c) * 32 + lane];
                mma_k32(acc, a[c][0], a[c][1], a[c][2], a[c][3], bf.x, bf.y);
            }
            {
                uint2 bf = g_w3frag[(nt * 5 + 4) * 32 + lane];
                mma_k16(acc, a40, a41, bf.x);
            }
            unsigned lo = (unsigned)(sgni(acc[0]) & 0xFF) |
                          ((unsigned)(sgni(acc[1]) & 0xFF) << 8);
            unsigned hi = (unsigned)(sgni(acc[2]) & 0xFF) |
                          ((unsigned)(sgni(acc[3]) & 0xFF) << 8);
            sepi[w][r][nt * 4 + q]     = (unsigned short)lo;
            sepi[w][r + 8][nt * 4 + q] = (unsigned short)hi;
        }
        __syncwarp();

        int px = lane & 15;
        int gx = x0 + px;
        if (gx < 252) {
            const unsigned* row32 = (const unsigned*)sepi[w][px];
            #pragma unroll
            for (int h = 0; h < 2; h++) {
                int og = (lane >> 4) + h * 2;
                uint2 v;
                v.x = row32[og * 2];
                v.y = row32[og * 2 + 1];
                g_s3v[og][((size_t)b * 252 + y) * 252 + gx] = v;
            }
        }
        __syncwarp();
    }
}

// ---------------------------------------------------------------------------
// Layer 4: ternary conv (32->2) + hardtanh -> fp32 out. Block = (b, 4-row
// group). (R9)
// ---------------------------------------------------------------------------
__global__ __launch_bounds__(256)
void l4_kernel(float* __restrict__ out) {
    __shared__ int sw[144];
    for (int i = threadIdx.x; i < 144; i += blockDim.x) sw[i] = g_w4p[i];
    __syncthreads();
    const int4* sw4 = (const int4*)sw;               // [(o*9+pos)*2 + half]

    int b  = blockIdx.x / 63;
    int yg = blockIdx.x % 63;
    int x  = threadIdx.x;
    if (x >= 250) return;
    int y0 = yg * 4;                                 // outputs y0..y0+3 (<250)

    int acc[4][2];
    #pragma unroll
    for (int p = 0; p < 4; p++) { acc[p][0] = 0; acc[p][1] = 0; }

    #pragma unroll
    for (int cc = 0; cc < 3; cc++) {
        uint2 d[6][4];                               // rows y0..y0+5, 4 planes
        #pragma unroll
        for (int r = 0; r < 6; r++) {
            int yi = y0 + r; if (yi > 251) yi = 251;
            size_t pix = ((size_t)b * 252 + yi) * 252 + (x + cc);
            #pragma unroll
            for (int q = 0; q < 4; q++) d[r][q] = g_s3v[q][pix];
        }
        #pragma unroll
        for (int ky = 0; ky < 3; ky++)
            #pragma unroll
            for (int o = 0; o < 2; o++) {
                int4 wa = sw4[(o * 9 + ky * 3 + cc) * 2 + 0];
                int4 wb = sw4[(o * 9 + ky * 3 + cc) * 2 + 1];
                #pragma unroll
                for (int p = 0; p < 4; p++) {
                    const uint2* dr = d[ky + p];
                    acc[p][o] = __dp4a((int)dr[0].x, wa.x, acc[p][o]);
                    acc[p][o] = __dp4a((int)dr[0].y, wa.y, acc[p][o]);
                    acc[p][o] = __dp4a((int)dr[1].x, wa.z, acc[p][o]);
                    acc[p][o] = __dp4a((int)dr[1].y, wa.w, acc[p][o]);
                    acc[p][o] = __dp4a((int)dr[2].x, wb.x, acc[p][o]);
                    acc[p][o] = __dp4a((int)dr[2].y, wb.y, acc[p][o]);
                    acc[p][o] = __dp4a((int)dr[3].x, wb.z, acc[p][o]);
                    acc[p][o] = __dp4a((int)dr[3].y, wb.w, acc[p][o]);
                }
            }
    }

    #pragma unroll
    for (int p = 0; p < 4; p++) {
        if (y0 + p < 250) {
            #pragma unroll
            for (int o = 0; o < 2; o++) {
                float v = fminf(fmaxf((float)acc[p][o], -1.f), 1.f);
                out[(size_t)b * 125000 + (size_t)o * 62500 + (size_t)(y0 + p) * 250 + x] = v;
            }
        }
    }
}

// ---------------------------------------------------------------------------
extern "C" void kernel_launch(void* const* d_in, const int* in_sizes, int n_in,
                              void* d_out, int out_size) {
    const float* x  = (const float*)d_in[0];
    const float* w1 = (const float*)d_in[1];
    const float* w2 = (const float*)d_in[2];
    const float* w3 = (const float*)d_in[3];
    const float* w4 = (const float*)d_in[4];
    float* out = (float*)d_out;

    prep_kernel<<<1, 256>>>(w1, w2, w3, w4);
    l1_kernel<<<8192, 256>>>(x);                    // 32*256*256 threads
    l2_kernel<<<32 * 64 * 2, 256>>>();              // block = (b, 4 rows, og)
    l3_kernel<<<32 * 252, 256>>>();                 // block = (b, output row)
    l4_kernel<<<32 * 63, 256>>>(out);               // block = (b, 4 rows)
}

// round 13
// speedup vs baseline: 1.5018x; 1.0243x over previous
#include <cuda_runtime.h>
#include <cstdint>

// ---------------------------------------------------------------------------
// MCNET binarized CNN (algebraic identities, see R0):
//   * sign(maxpool(hardtanh(v))) == sign(max(v))
//   * sign(hardtanh(int n)) == sign(n)
//   * L2..L4 activations are ternary {-1,0,+1} int8 sign maps
// R13: l1 (R12) / l2 (R9) frozen. l3: 4 output rows/block (1.5x staging),
// vectorized epilogue (2 STS.64 + 2 LDS.128 + 2 STG.128) with the s3
// byte->channel permutation absorbed into prep's w4 packing. s3 stored
// interleaved 32B/pixel so l4 loads are LDG.128.
// ---------------------------------------------------------------------------

static __device__ uint2 g_s1[32u * 256 * 256];         // [b,y,x, 8ch]  16.8 MB
static __device__ int4  g_s2[32u * 254 * 254];         // [b,y,x,16ch]  33.0 MB
static __device__ uint4 g_s3x[32u * 252 * 252 * 2];    // [b,y,x][2]: 32B/px  65 MB

static __device__ float g_w1f[216];    // [o=8][c=3][ky][kx] as float +-1/0
static __device__ int   g_w2p[288];    // [o=16][9 pos][2 packs of 4ch]
static __device__ uint2 g_w3frag[640]; // [(nt*5+chunk)*32 + lane] = {b0,b1} mma frags
static __device__ int   g_w4p[144];    // [o=2][9 pos][8 words], permuted channels

__device__ __forceinline__ int sgnf(float v) { return (v > 0.f) - (v < 0.f); }
__device__ __forceinline__ int sgni(int v)   { return (v > 0) - (v < 0); }
__device__ __forceinline__ int pack4(int a, int b, int c, int d) {
    return (a & 0xFF) | ((b & 0xFF) << 8) | ((c & 0xFF) << 16) | ((d & 0xFF) << 24);
}

// ---- mma helpers ----------------------------------------------------------
__device__ __forceinline__ unsigned smem_u32(const void* p) {
    return (unsigned)__cvta_generic_to_shared(p);
}
__device__ __forceinline__ void ldmatrix_x4(unsigned& a0, unsigned& a1,
                                            unsigned& a2, unsigned& a3, unsigned addr) {
    asm volatile("ldmatrix.sync.aligned.m8n8.x4.shared.b16 {%0,%1,%2,%3}, [%4];"
                 : "=r"(a0), "=r"(a1), "=r"(a2), "=r"(a3) : "r"(addr));
}
__device__ __forceinline__ void ldmatrix_x2(unsigned& a0, unsigned& a1, unsigned addr) {
    asm volatile("ldmatrix.sync.aligned.m8n8.x2.shared.b16 {%0,%1}, [%2];"
                 : "=r"(a0), "=r"(a1) : "r"(addr));
}
__device__ __forceinline__ void mma_k32(int* c, unsigned a0, unsigned a1,
                                        unsigned a2, unsigned a3,
                                        unsigned b0, unsigned b1) {
    asm volatile("mma.sync.aligned.m16n8k32.row.col.s32.s8.s8.s32 "
                 "{%0,%1,%2,%3},{%4,%5,%6,%7},{%8,%9},{%0,%1,%2,%3};"
                 : "+r"(c[0]), "+r"(c[1]), "+r"(c[2]), "+r"(c[3])
                 : "r"(a0), "r"(a1), "r"(a2), "r"(a3), "r"(b0), "r"(b1));
}
__device__ __forceinline__ void mma_k16(int* c, unsigned a0, unsigned a1, unsigned b0) {
    asm volatile("mma.sync.aligned.m16n8k16.row.col.s32.s8.s8.s32 "
                 "{%0,%1,%2,%3},{%4,%5},{%6},{%0,%1,%2,%3};"
                 : "+r"(c[0]), "+r"(c[1]), "+r"(c[2]), "+r"(c[3])
                 : "r"(a0), "r"(a1), "r"(b0));
}

// ---------------------------------------------------------------------------
__global__ void prep_kernel(const float* __restrict__ w1, const float* __restrict__ w2,
                            const float* __restrict__ w3, const float* __restrict__ w4) {
    int t = threadIdx.x;
    for (int i = t; i < 216; i += blockDim.x) g_w1f[i] = (float)sgnf(w1[i]);
    for (int i = t; i < 288; i += blockDim.x) {
        int h = i & 1, pos = (i >> 1) % 9, o = i / 18;
        int ky = pos / 3, kx = pos % 3;
        int s[4];
        #pragma unroll
        for (int j = 0; j < 4; j++)
            s[j] = sgnf(w2[((o * 8 + (4 * h + j)) * 3 + ky) * 3 + kx]);
        g_w2p[i] = pack4(s[0], s[1], s[2], s[3]);
    }
    // w3 -> mma B fragments (layout as R11)
    for (int i = t; i < 640; i += blockDim.x) {
        int lane = i & 31, nc = i >> 5;
        int nt = nc / 5, c = nc % 5;
        int oc = nt * 8 + (lane >> 2);
        int chb = (lane & 3) * 4;
        int tapA = (c < 4) ? 2 * c : 8;
        int sA[4];
        #pragma unroll
        for (int j = 0; j < 4; j++)
            sA[j] = sgnf(w3[((oc * 16 + chb + j) * 3 + tapA / 3) * 3 + tapA % 3]);
        unsigned b0 = (unsigned)pack4(sA[0], sA[1], sA[2], sA[3]);
        unsigned b1 = 0;
        if (c < 4) {
            int tapB = 2 * c + 1;
            int sB[4];
            #pragma unroll
            for (int j = 0; j < 4; j++)
                sB[j] = sgnf(w3[((oc * 16 + chb + j) * 3 + tapB / 3) * 3 + tapB % 3]);
            b1 = (unsigned)pack4(sB[0], sB[1], sB[2], sB[3]);
        }
        g_w3frag[i] = make_uint2(b0, b1);
    }
    // w4: s3 pixel byte m holds channel oc(m) = ((m&7)>>1)*8 + (m>>3)*2 + (m&1)
    // (q = m>>3 from mma lane%4, nt = (m&7)>>1, hl = m&1). Pack w4 to match.
    for (int i = t; i < 144; i += blockDim.x) {
        int wrd = i & 7, pos = (i >> 3) % 9, o = i / 72;
        int ky = pos / 3, kx = pos % 3;
        int s[4];
        #pragma unroll
        for (int j = 0; j < 4; j++) {
            int m = 4 * wrd + j;
            int oc = ((m & 7) >> 1) * 8 + ((m >> 3) << 1) + (m & 1);
            s[j] = sgnf(w4[((o * 32 + oc) * 3 + ky) * 3 + kx]);
        }
        g_w4p[i] = pack4(s[0], s[1], s[2], s[3]);
    }
}

// ---------------------------------------------------------------------------
// Layer 1: fp conv (3->8), pad 1.0, fused hardtanh+maxpool+sign. (R12)
// ---------------------------------------------------------------------------
__global__ __launch_bounds__(256)
void l1_kernel(const float* __restrict__ x) {
    __shared__ __align__(16) float sw[216];          // [(c*9+ky*3+kx)*8 + o]
    for (int i = threadIdx.x; i < 216; i += 256) {
        int o = i & 7, rest = i >> 3;
        int kx = rest % 3, ky = (rest / 3) % 3, c = rest / 9;
        sw[i] = g_w1f[((o * 3 + c) * 3 + ky) * 3 + kx];
    }
    __syncthreads();
    const float4* sw4 = (const float4*)sw;           // [tap*2 + half]

    int t = blockIdx.x * blockDim.x + threadIdx.x;   // 32*256*256 threads exact
    int px = t & 255;
    int py = (t >> 8) & 255;
    int b  = t >> 16;

    float acc[4][8];
    #pragma unroll
    for (int p = 0; p < 4; p++)
        #pragma unroll
        for (int o = 0; o < 8; o++) acc[p][o] = 0.f;

    int gy0 = 2 * py - 1;
    int gx0 = 2 * px - 1;
    bool interior = (px - 1u < 254u) && (py - 1u < 254u);

    #pragma unroll
    for (int c = 0; c < 3; c++) {
        float p[4][4];
        const float* xc = x + ((size_t)b * 3 + c) * 512 * 512;
        if (interior) {
            #pragma unroll
            for (int r = 0; r < 4; r++)
                #pragma unroll
                for (int cc = 0; cc < 4; cc++)
                    p[r][cc] = __ldg(xc + (gy0 + r) * 512 + (gx0 + cc));
        } else {
            #pragma unroll
            for (int r = 0; r < 4; r++) {
                int gy = gy0 + r;
                bool rok = (unsigned)gy < 512u;
                #pragma unroll
                for (int cc = 0; cc < 4; cc++) {
                    int gx = gx0 + cc;
                    bool ok = rok && ((unsigned)gx < 512u);
                    p[r][cc] = ok ? __ldg(xc + gy * 512 + gx) : 1.0f;
                }
            }
        }
        #pragma unroll
        for (int ky = 0; ky < 3; ky++)
            #pragma unroll
            for (int kx = 0; kx < 3; kx++) {
                int tap = c * 9 + ky * 3 + kx;
                float4 wa = sw4[tap * 2 + 0];        // o = 0..3
                float4 wb = sw4[tap * 2 + 1];        // o = 4..7
                float wv[8] = {wa.x, wa.y, wa.z, wa.w, wb.x, wb.y, wb.z, wb.w};
                #pragma unroll
                for (int o = 0; o < 8; o++) {
                    float w = wv[o];
                    #pragma unroll
                    for (int dy = 0; dy < 2; dy++)
                        #pragma unroll
                        for (int dx = 0; dx < 2; dx++)
                            acc[dy * 2 + dx][o] = fmaf(p[ky + dy][kx + dx], w,
                                                       acc[dy * 2 + dx][o]);
                }
            }
    }

    int s[8];
    #pragma unroll
    for (int o = 0; o < 8; o++) {
        float m = fmaxf(fmaxf(acc[0][o], acc[1][o]), fmaxf(acc[2][o], acc[3][o]));
        s[o] = sgnf(m);
    }
    uint2 out;
    out.x = (unsigned)pack4(s[0], s[1], s[2], s[3]);
    out.y = (unsigned)pack4(s[4], s[5], s[6], s[7]);
    g_s1[((size_t)b * 256 + py) * 256 + px] = out;
}

// ---------------------------------------------------------------------------
// Layer 2: ternary conv (8->16). Block = (b, 4-row group, og of 8 oc). (R9)
// ---------------------------------------------------------------------------
__global__ __launch_bounds__(256)
void l2_kernel() {
    __shared__ int sw[144];                          // this og's 72 int2
    int blk = blockIdx.x;
    int og  = blk & 1;
    int yg  = (blk >> 1) & 63;
    int b   = blk >> 7;
    for (int i = threadIdx.x; i < 144; i += blockDim.x) sw[i] = g_w2p[og * 144 + i];
    __syncthreads();
    const int2* sw2 = (const int2*)sw;               // [o*9 + pos], o in 0..7

    int x = threadIdx.x;
    if (x >= 254) return;
    int y0 = yg * 4;                                 // outputs y0..y0+3 (<254)

    int acc[4][8];
    #pragma unroll
    for (int p = 0; p < 4; p++)
        #pragma unroll
        for (int o = 0; o < 8; o++) acc[p][o] = 0;

    #pragma unroll
    for (int cc = 0; cc < 3; cc++) {
        uint2 d[6];                                  // input rows y0..y0+5 (clamped)
        #pragma unroll
        for (int r = 0; r < 6; r++) {
            int yi = y0 + r; if (yi > 255) yi = 255;
            d[r] = g_s1[((size_t)b * 256 + yi) * 256 + (x + cc)];
        }
        #pragma unroll
        for (int ky = 0; ky < 3; ky++)
            #pragma unroll
            for (int o = 0; o < 8; o++) {
                int2 w = sw2[o * 9 + ky * 3 + cc];
                #pragma unroll
                for (int p = 0; p < 4; p++) {
                    acc[p][o] = __dp4a((int)d[ky + p].x, w.x, acc[p][o]);
                    acc[p][o] = __dp4a((int)d[ky + p].y, w.y, acc[p][o]);
                }
            }
    }

    uint2* s2h = (uint2*)g_s2;                       // pixel = 2 uint2 halves
    #pragma unroll
    for (int p = 0; p < 4; p++) {
        if (y0 + p < 254) {
            uint2 v;
            v.x = (unsigned)pack4(sgni(acc[p][0]), sgni(acc[p][1]),
                                  sgni(acc[p][2]), sgni(acc[p][3]));
            v.y = (unsigned)pack4(sgni(acc[p][4]), sgni(acc[p][5]),
                                  sgni(acc[p][6]), sgni(acc[p][7]));
            s2h[(((size_t)b * 254 + (y0 + p)) * 254 + x) * 2 + og] = v;
        }
    }
}

// ---------------------------------------------------------------------------
// Layer 3: ternary conv (16->32) on int8 tensor cores.
// Block = (b, 4 output rows): stages 6 s2 rows once (1.5x redundancy vs 3x).
// Warp-tile = 16 px x 32 oc. Epilogue: per-lane sign u16s accumulated over
// nt in regs -> 2 STS.64; 16 lanes read 32B/px via 2 LDS.128 and store
// 2 STG.128 into interleaved g_s3x. Channel order handled by w4 packing.
// ---------------------------------------------------------------------------
__global__ __launch_bounds__(256)
void l3_kernel() {
    __shared__ __align__(16) uint4 sraw[6][256];               // 16B pixel vecs
    __shared__ __align__(16) unsigned short sepi[8][16][16];   // [w][px][q*4+nt]

    int blk = blockIdx.x;
    int yg = blk % 63;
    int b  = blk / 63;
    int y0 = yg * 4;

    const uint4* src = (const uint4*)g_s2;
    for (int i = threadIdx.x; i < 6 * 254; i += 256) {
        int r = i / 254, cx = i % 254;
        sraw[r][cx] = src[((size_t)b * 254 + (y0 + r)) * 254 + cx];
    }
    __syncthreads();

    int lane = threadIdx.x & 31;
    int w    = threadIdx.x >> 5;
    int grp = lane >> 3, li = lane & 7;
    int q = lane & 3;
    int r = lane >> 2;

    for (int t = w; t < 64; t += 8) {
        int ry = t >> 4;                             // output row within group
        int x0 = (t & 15) * 16;

        // A fragments: chunks 0..3 (taps 2c,2c+1) and chunk 4 (tap 8)
        unsigned a[4][4];
        unsigned a40, a41;
        #pragma unroll
        for (int c = 0; c < 4; c++) {
            int tap = 2 * c + (grp >> 1);
            int ky = tap / 3, kx = tap % 3;
            int col = x0 + ((grp & 1) << 3) + li + kx;
            if (col > 253) col = 253;
            ldmatrix_x4(a[c][0], a[c][1], a[c][2], a[c][3],
                        smem_u32(&sraw[ry + ky][col]));
        }
        {
            int col = x0 + ((grp & 1) << 3) + li + 2;    // ky=2, kx=2
            if (col > 253) col = 253;
            ldmatrix_x2(a40, a41, smem_u32(&sraw[ry + 2][col]));
        }

        unsigned lo01 = 0, lo23 = 0, hi01 = 0, hi23 = 0;
        #pragma unroll
        for (int nt = 0; nt < 4; nt++) {
            int acc[4] = {0, 0, 0, 0};
            #pragma unroll
            for (int c = 0; c < 4; c++) {
                uint2 bf = g_w3frag[(nt * 5 + c) * 32 + lane];
                mma_k32(acc, a[c][0], a[c][1], a[c][2], a[c][3], bf.x, bf.y);
            }
            {
                uint2 bf = g_w3frag[(nt * 5 + 4) * 32 + lane];
                mma_k16(acc, a40, a41, bf.x);
            }
            unsigned lo = (unsigned)(sgni(acc[0]) & 0xFF) |
                          ((unsigned)(sgni(acc[1]) & 0xFF) << 8);
            unsigned hi = (unsigned)(sgni(acc[2]) & 0xFF) |
                          ((unsigned)(sgni(acc[3]) & 0xFF) << 8);
            if (nt == 0)      { lo01 = lo;        hi01 = hi;        }
            else if (nt == 1) { lo01 |= lo << 16; hi01 |= hi << 16; }
            else if (nt == 2) { lo23 = lo;        hi23 = hi;        }
            else              { lo23 |= lo << 16; hi23 |= hi << 16; }
        }
        *(uint2*)&sepi[w][r][q * 4]     = make_uint2(lo01, lo23);
        *(uint2*)&sepi[w][r + 8][q * 4] = make_uint2(hi01, hi23);
        __syncwarp();

        if (lane < 16) {
            int gx = x0 + lane;
            if (gx < 252) {
                const uint4* rp = (const uint4*)&sepi[w][lane][0];
                size_t pix = ((size_t)b * 252 + (y0 + ry)) * 252 + gx;
                g_s3x[pix * 2 + 0] = rp[0];
                g_s3x[pix * 2 + 1] = rp[1];
            }
        }
        __syncwarp();
    }
}

// ---------------------------------------------------------------------------
// Layer 4: ternary conv (32->2) + hardtanh -> fp32 out. Block = (b, 4-row
// group). Thread = one x, up to 4 y rows, both oc. 32B/px LDG.128 loads;
// weight words permuted to match s3 byte order (see prep).
// ---------------------------------------------------------------------------
__global__ __launch_bounds__(256)
void l4_kernel(float* __restrict__ out) {
    __shared__ int sw[144];
    for (int i = threadIdx.x; i < 144; i += blockDim.x) sw[i] = g_w4p[i];
    __syncthreads();
    const int4* sw4 = (const int4*)sw;               // [(o*9+pos)*2 + half]

    int b  = blockIdx.x / 63;
    int yg = blockIdx.x % 63;
    int x  = threadIdx.x;
    if (x >= 250) return;
    int y0 = yg * 4;                                 // outputs y0..y0+3 (<250)

    int acc[4][2];
    #pragma unroll
    for (int p = 0; p < 4; p++) { acc[p][0] = 0; acc[p][1] = 0; }

    #pragma unroll
    for (int cc = 0; cc < 3; cc++) {
        uint4 d[6][2];                               // rows y0..y0+5, 32B each
        #pragma unroll
        for (int r = 0; r < 6; r++) {
            int yi = y0 + r; if (yi > 251) yi = 251;
            size_t pix = ((size_t)b * 252 + yi) * 252 + (x + cc);
            d[r][0] = g_s3x[pix * 2 + 0];
            d[r][1] = g_s3x[pix * 2 + 1];
        }
        #pragma unroll
        for (int ky = 0; ky < 3; ky++)
            #pragma unroll
            for (int o = 0; o < 2; o++) {
                int4 wa = sw4[(o * 9 + ky * 3 + cc) * 2 + 0];
                int4 wb = sw4[(o * 9 + ky * 3 + cc) * 2 + 1];
                #pragma unroll
                for (int p = 0; p < 4; p++) {
                    const uint4* dr = d[ky + p];
                    acc[p][o] = __dp4a((int)dr[0].x, wa.x, acc[p][o]);
                    acc[p][o] = __dp4a((int)dr[0].y, wa.y, acc[p][o]);
                    acc[p][o] = __dp4a((int)dr[0].z, wa.z, acc[p][o]);
                    acc[p][o] = __dp4a((int)dr[0].w, wa.w, acc[p][o]);
                    acc[p][o] = __dp4a((int)dr[1].x, wb.x, acc[p][o]);
                    acc[p][o] = __dp4a((int)dr[1].y, wb.y, acc[p][o]);
                    acc[p][o] = __dp4a((int)dr[1].z, wb.z, acc[p][o]);
                    acc[p][o] = __dp4a((int)dr[1].w, wb.w, acc[p][o]);
                }
            }
    }

    #pragma unroll
    for (int p = 0; p < 4; p++) {
        if (y0 + p < 250) {
            #pragma unroll
            for (int o = 0; o < 2; o++) {
                float v = fminf(fmaxf((float)acc[p][o], -1.f), 1.f);
                out[(size_t)b * 125000 + (size_t)o * 62500 + (size_t)(y0 + p) * 250 + x] = v;
            }
        }
    }
}

// ---------------------------------------------------------------------------
extern "C" void kernel_launch(void* const* d_in, const int* in_sizes, int n_in,
                              void* d_out, int out_size) {
    const float* x  = (const float*)d_in[0];
    const float* w1 = (const float*)d_in[1];
    const float* w2 = (const float*)d_in[2];
    const float* w3 = (const float*)d_in[3];
    const float* w4 = (const float*)d_in[4];
    float* out = (float*)d_out;

    prep_kernel<<<1, 256>>>(w1, w2, w3, w4);
    l1_kernel<<<8192, 256>>>(x);                    // 32*256*256 threads
    l2_kernel<<<32 * 64 * 2, 256>>>();              // block = (b, 4 rows, og)
    l3_kernel<<<32 * 63, 256>>>();                  // block = (b, 4 rows)
    l4_kernel<<<32 * 63, 256>>>(out);               // block = (b, 4 rows)
}

// round 16
// speedup vs baseline: 1.7036x; 1.1344x over previous
#include <cuda_runtime.h>
#include <cstdint>

// ---------------------------------------------------------------------------
// MCNET binarized CNN (algebraic identities, see R0):
//   * sign(maxpool(hardtanh(v))) == sign(max(v))
//   * sign(hardtanh(int n)) == sign(n)
//   * L2..L4 activations are ternary {-1,0,+1} int8 sign maps
// R15 = R14 with the l2 misalignment fixed: ldmatrix (needs 16B-aligned rows;
// s1 pixels are 8B) replaced by 12 LDS.32 building the identical m16n8k32
// A fragments. l1 (R12), l3 (R13), l4 (R13) frozen; s2 byte permutation
// absorbed in prep's w3frag packing.
// ---------------------------------------------------------------------------

static __device__ uint2 g_s1[32u * 256 * 256];         // [b,y,x, 8ch]  16.8 MB
static __device__ int4  g_s2[32u * 254 * 254];         // [b,y,x,16ch] (perm bytes)
static __device__ uint4 g_s3x[32u * 252 * 252 * 2];    // [b,y,x][2]: 32B/px  65 MB

static __device__ float g_w1f[216];    // [o=8][c=3][ky][kx] as float +-1/0
static __device__ uint2 g_w2frag[192]; // [(nt*3+ky)*32+lane] = {b0,b1} l2 mma frags
static __device__ uint2 g_w3frag[640]; // [(nt*5+chunk)*32+lane] l3 frags (perm ch)
static __device__ int   g_w4p[144];    // [o=2][9 pos][8 words], permuted channels

__device__ __forceinline__ int sgnf(float v) { return (v > 0.f) - (v < 0.f); }
__device__ __forceinline__ int sgni(int v)   { return (v > 0) - (v < 0); }
__device__ __forceinline__ int pack4(int a, int b, int c, int d) {
    return (a & 0xFF) | ((b & 0xFF) << 8) | ((c & 0xFF) << 16) | ((d & 0xFF) << 24);
}

// ---- mma helpers ----------------------------------------------------------
__device__ __forceinline__ unsigned smem_u32(const void* p) {
    return (unsigned)__cvta_generic_to_shared(p);
}
__device__ __forceinline__ void ldmatrix_x4(unsigned& a0, unsigned& a1,
                                            unsigned& a2, unsigned& a3, unsigned addr) {
    asm volatile("ldmatrix.sync.aligned.m8n8.x4.shared.b16 {%0,%1,%2,%3}, [%4];"
                 : "=r"(a0), "=r"(a1), "=r"(a2), "=r"(a3) : "r"(addr));
}
__device__ __forceinline__ void ldmatrix_x2(unsigned& a0, unsigned& a1, unsigned addr) {
    asm volatile("ldmatrix.sync.aligned.m8n8.x2.shared.b16 {%0,%1}, [%2];"
                 : "=r"(a0), "=r"(a1) : "r"(addr));
}
__device__ __forceinline__ void mma_k32(int* c, unsigned a0, unsigned a1,
                                        unsigned a2, unsigned a3,
                                        unsigned b0, unsigned b1) {
    asm volatile("mma.sync.aligned.m16n8k32.row.col.s32.s8.s8.s32 "
                 "{%0,%1,%2,%3},{%4,%5,%6,%7},{%8,%9},{%0,%1,%2,%3};"
                 : "+r"(c[0]), "+r"(c[1]), "+r"(c[2]), "+r"(c[3])
                 : "r"(a0), "r"(a1), "r"(a2), "r"(a3), "r"(b0), "r"(b1));
}
__device__ __forceinline__ void mma_k16(int* c, unsigned a0, unsigned a1, unsigned b0) {
    asm volatile("mma.sync.aligned.m16n8k16.row.col.s32.s8.s8.s32 "
                 "{%0,%1,%2,%3},{%4,%5},{%6},{%0,%1,%2,%3};"
                 : "+r"(c[0]), "+r"(c[1]), "+r"(c[2]), "+r"(c[3])
                 : "r"(a0), "r"(a1), "r"(b0));
}

// s2 byte m holds l2-output channel perm2(m) (from l2's mma epilogue):
__device__ __forceinline__ int perm2(int m) {
    return 8 * ((m >> 1) & 1) + 2 * (m >> 2) + (m & 1);
}

// ---------------------------------------------------------------------------
__global__ void prep_kernel(const float* __restrict__ w1, const float* __restrict__ w2,
                            const float* __restrict__ w3, const float* __restrict__ w4) {
    int t = threadIdx.x;
    for (int i = t; i < 216; i += blockDim.x) g_w1f[i] = (float)sgnf(w1[i]);
    // w2 -> l2 mma B fragments. k32 chunk for ky: k = pxoff*8 + ch,
    // weight = w2[oc][ch][ky][kx=pxoff] (pxoff 3 -> 0 pad).
    for (int i = t; i < 192; i += blockDim.x) {
        int lane = i & 31, nc = i >> 5;
        int nt = nc / 3, ky = nc % 3;
        int oc = nt * 8 + (lane >> 2);
        int s0[4], s1v[4];
        #pragma unroll
        for (int j = 0; j < 4; j++) {
            int k = (lane & 3) * 4 + j;              // 0..15
            int px = k >> 3, ch = k & 7;
            s0[j] = sgnf(w2[((oc * 8 + ch) * 3 + ky) * 3 + px]);
            int k2 = k + 16;                         // 16..31
            int px2 = k2 >> 3;                       // 2 or 3
            s1v[j] = (px2 < 3) ? sgnf(w2[((oc * 8 + ch) * 3 + ky) * 3 + px2]) : 0;
        }
        g_w2frag[i] = make_uint2((unsigned)pack4(s0[0], s0[1], s0[2], s0[3]),
                                 (unsigned)pack4(s1v[0], s1v[1], s1v[2], s1v[3]));
    }
    // w3 -> mma B fragments (R11 layout, input-channel index permuted to
    // match the l2-epilogue s2 byte order).
    for (int i = t; i < 640; i += blockDim.x) {
        int lane = i & 31, nc = i >> 5;
        int nt = nc / 5, c = nc % 5;
        int oc = nt * 8 + (lane >> 2);
        int chb = (lane & 3) * 4;
        int tapA = (c < 4) ? 2 * c : 8;
        int sA[4];
        #pragma unroll
        for (int j = 0; j < 4; j++) {
            int chp = perm2(chb + j);
            sA[j] = sgnf(w3[((oc * 16 + chp) * 3 + tapA / 3) * 3 + tapA % 3]);
        }
        unsigned b0 = (unsigned)pack4(sA[0], sA[1], sA[2], sA[3]);
        unsigned b1 = 0;
        if (c < 4) {
            int tapB = 2 * c + 1;
            int sB[4];
            #pragma unroll
            for (int j = 0; j < 4; j++) {
                int chp = perm2(chb + j);
                sB[j] = sgnf(w3[((oc * 16 + chp) * 3 + tapB / 3) * 3 + tapB % 3]);
            }
            b1 = (unsigned)pack4(sB[0], sB[1], sB[2], sB[3]);
        }
        g_w3frag[i] = make_uint2(b0, b1);
    }
    // w4: s3 pixel byte m holds channel oc(m) = ((m&7)>>1)*8 + (m>>3)*2 + (m&1)
    for (int i = t; i < 144; i += blockDim.x) {
        int wrd = i & 7, pos = (i >> 3) % 9, o = i / 72;
        int ky = pos / 3, kx = pos % 3;
        int s[4];
        #pragma unroll
        for (int j = 0; j < 4; j++) {
            int m = 4 * wrd + j;
            int oc = ((m & 7) >> 1) * 8 + ((m >> 3) << 1) + (m & 1);
            s[j] = sgnf(w4[((o * 32 + oc) * 3 + ky) * 3 + kx]);
        }
        g_w4p[i] = pack4(s[0], s[1], s[2], s[3]);
    }
}

// ---------------------------------------------------------------------------
// Layer 1: fp conv (3->8), pad 1.0, fused hardtanh+maxpool+sign. (R12)
// ---------------------------------------------------------------------------
__global__ __launch_bounds__(256)
void l1_kernel(const float* __restrict__ x) {
    __shared__ __align__(16) float sw[216];          // [(c*9+ky*3+kx)*8 + o]
    for (int i = threadIdx.x; i < 216; i += 256) {
        int o = i & 7, rest = i >> 3;
        int kx = rest % 3, ky = (rest / 3) % 3, c = rest / 9;
        sw[i] = g_w1f[((o * 3 + c) * 3 + ky) * 3 + kx];
    }
    __syncthreads();
    const float4* sw4 = (const float4*)sw;           // [tap*2 + half]

    int t = blockIdx.x * blockDim.x + threadIdx.x;   // 32*256*256 threads exact
    int px = t & 255;
    int py = (t >> 8) & 255;
    int b  = t >> 16;

    float acc[4][8];
    #pragma unroll
    for (int p = 0; p < 4; p++)
        #pragma unroll
        for (int o = 0; o < 8; o++) acc[p][o] = 0.f;

    int gy0 = 2 * py - 1;
    int gx0 = 2 * px - 1;
    bool interior = (px - 1u < 254u) && (py - 1u < 254u);

    #pragma unroll
    for (int c = 0; c < 3; c++) {
        float p[4][4];
        const float* xc = x + ((size_t)b * 3 + c) * 512 * 512;
        if (interior) {
            #pragma unroll
            for (int r = 0; r < 4; r++)
                #pragma unroll
                for (int cc = 0; cc < 4; cc++)
                    p[r][cc] = __ldg(xc + (gy0 + r) * 512 + (gx0 + cc));
        } else {
            #pragma unroll
            for (int r = 0; r < 4; r++) {
                int gy = gy0 + r;
                bool rok = (unsigned)gy < 512u;
                #pragma unroll
                for (int cc = 0; cc < 4; cc++) {
                    int gx = gx0 + cc;
                    bool ok = rok && ((unsigned)gx < 512u);
                    p[r][cc] = ok ? __ldg(xc + gy * 512 + gx) : 1.0f;
                }
            }
        }
        #pragma unroll
        for (int ky = 0; ky < 3; ky++)
            #pragma unroll
            for (int kx = 0; kx < 3; kx++) {
                int tap = c * 9 + ky * 3 + kx;
                float4 wa = sw4[tap * 2 + 0];        // o = 0..3
                float4 wb = sw4[tap * 2 + 1];        // o = 4..7
                float wv[8] = {wa.x, wa.y, wa.z, wa.w, wb.x, wb.y, wb.z, wb.w};
                #pragma unroll
                for (int o = 0; o < 8; o++) {
                    float w = wv[o];
                    #pragma unroll
                    for (int dy = 0; dy < 2; dy++)
                        #pragma unroll
                        for (int dx = 0; dx < 2; dx++)
                            acc[dy * 2 + dx][o] = fmaf(p[ky + dy][kx + dx], w,
                                                       acc[dy * 2 + dx][o]);
                }
            }
    }

    int s[8];
    #pragma unroll
    for (int o = 0; o < 8; o++) {
        float m = fmaxf(fmaxf(acc[0][o], acc[1][o]), fmaxf(acc[2][o], acc[3][o]));
        s[o] = sgnf(m);
    }
    uint2 out;
    out.x = (unsigned)pack4(s[0], s[1], s[2], s[3]);
    out.y = (unsigned)pack4(s[4], s[5], s[6], s[7]);
    g_s1[((size_t)b * 256 + py) * 256 + px] = out;
}

// ---------------------------------------------------------------------------
// Layer 2: ternary conv (8->16) on int8 tensor cores.
// Block = (b, 4 output rows). Stages 6 s1 rows. Warp-tile = 16 px x 16 oc:
// 3 k32 mmas per n-tile (ky chunks; A row = 4 consecutive 8B pixels, kx=3
// weights zero). A fragments built with LDS.32 (4B-aligned; ldmatrix would
// need 16B rows). Epilogue: sign u16s -> STS.32; 16 lanes LDS.128+STG.128
// into g_s2 (byte order perm2, compensated in w3frag).
// ---------------------------------------------------------------------------
__global__ __launch_bounds__(256)
void l2_kernel() {
    __shared__ __align__(16) uint2 srow[6][260];               // 8B pixel vecs
    __shared__ __align__(16) unsigned short sepi[8][16][8];    // [w][px][q*2+nt]

    int blk = blockIdx.x;
    int yg = blk & 63;
    int b  = blk >> 6;
    int y0 = yg * 4;

    for (int i = threadIdx.x; i < 6 * 256; i += 256) {
        int r = i >> 8, cx = i & 255;
        int yi = y0 + r; if (yi > 255) yi = 255;
        srow[r][cx] = g_s1[((size_t)b * 256 + yi) * 256 + cx];
    }
    // zero the 4 pad columns so A-row reads past col 255 are deterministic
    if (threadIdx.x < 24) {
        int r = threadIdx.x / 4, cx = 256 + (threadIdx.x & 3);
        srow[r][cx] = make_uint2(0u, 0u);
    }
    __syncthreads();

    int lane = threadIdx.x & 31;
    int w    = threadIdx.x >> 5;
    int q = lane & 3;
    int r = lane >> 2;

    for (int t = w; t < 64; t += 8) {
        int ry = t >> 4;
        int x0 = (t & 15) * 16;

        // A fragments per ky, built with LDS.32 (layout == ldmatrix.x4):
        //   a0: row r,   k bytes q*4..q*4+3   (pixels x0+r .. x0+r+1)
        //   a1: row r+8, same k               a2/a3: +16B (pixels +2..+3)
        unsigned a[3][4];
        #pragma unroll
        for (int ky = 0; ky < 3; ky++) {
            const char* b0 = (const char*)&srow[ry + ky][x0 + r];
            const char* b1 = (const char*)&srow[ry + ky][x0 + r + 8];
            a[ky][0] = *(const unsigned*)(b0 + q * 4);
            a[ky][1] = *(const unsigned*)(b1 + q * 4);
            a[ky][2] = *(const unsigned*)(b0 + 16 + q * 4);
            a[ky][3] = *(const unsigned*)(b1 + 16 + q * 4);
        }

        unsigned lo01[2], hi01[2];
        #pragma unroll
        for (int nt = 0; nt < 2; nt++) {
            int acc[4] = {0, 0, 0, 0};
            #pragma unroll
            for (int ky = 0; ky < 3; ky++) {
                uint2 bf = g_w2frag[(nt * 3 + ky) * 32 + lane];
                mma_k32(acc, a[ky][0], a[ky][1], a[ky][2], a[ky][3], bf.x, bf.y);
            }
            lo01[nt] = (unsigned)(sgni(acc[0]) & 0xFF) |
                       ((unsigned)(sgni(acc[1]) & 0xFF) << 8);
            hi01[nt] = (unsigned)(sgni(acc[2]) & 0xFF) |
                       ((unsigned)(sgni(acc[3]) & 0xFF) << 8);
        }
        *(unsigned*)&sepi[w][r][q * 2]     = lo01[0] | (lo01[1] << 16);
        *(unsigned*)&sepi[w][r + 8][q * 2] = hi01[0] | (hi01[1] << 16);
        __syncwarp();

        if (lane < 16) {
            int gx = x0 + lane;
            if (gx < 254 && (y0 + ry) < 254) {
                g_s2[((size_t)b * 254 + (y0 + ry)) * 254 + gx] =
                    *(const int4*)&sepi[w][lane][0];
            }
        }
        __syncwarp();
    }
}

// ---------------------------------------------------------------------------
// Layer 3: ternary conv (16->32) on int8 tensor cores. (R13; channel perm
// of s2 handled in w3frag packing)
// ---------------------------------------------------------------------------
__global__ __launch_bounds__(256)
void l3_kernel() {
    __shared__ __align__(16) uint4 sraw[6][256];               // 16B pixel vecs
    __shared__ __align__(16) unsigned short sepi[8][16][16];   // [w][px][q*4+nt]

    int blk = blockIdx.x;
    int yg = blk % 63;
    int b  = blk / 63;
    int y0 = yg * 4;

    const uint4* src = (const uint4*)g_s2;
    for (int i = threadIdx.x; i < 6 * 254; i += 256) {
        int r = i / 254, cx = i % 254;
        sraw[r][cx] = src[((size_t)b * 254 + (y0 + r)) * 254 + cx];
    }
    __syncthreads();

    int lane = threadIdx.x & 31;
    int w    = threadIdx.x >> 5;
    int grp = lane >> 3, li = lane & 7;
    int q = lane & 3;
    int r = lane >> 2;

    for (int t = w; t < 64; t += 8) {
        int ry = t >> 4;
        int x0 = (t & 15) * 16;

        unsigned a[4][4];
        unsigned a40, a41;
        #pragma unroll
        for (int c = 0; c < 4; c++) {
            int tap = 2 * c + (grp >> 1);
            int ky = tap / 3, kx = tap % 3;
            int col = x0 + ((grp & 1) << 3) + li + kx;
            if (col > 253) col = 253;
            ldmatrix_x4(a[c][0], a[c][1], a[c][2], a[c][3],
                        smem_u32(&sraw[ry + ky][col]));
        }
        {
            int col = x0 + ((grp & 1) << 3) + li + 2;    // ky=2, kx=2
            if (col > 253) col = 253;
            ldmatrix_x2(a40, a41, smem_u32(&sraw[ry + 2][col]));
        }

        unsigned lo01 = 0, lo23 = 0, hi01 = 0, hi23 = 0;
        #pragma unroll
        for (int nt = 0; nt < 4; nt++) {
            int acc[4] = {0, 0, 0, 0};
            #pragma unroll
            for (int c = 0; c < 4; c++) {
                uint2 bf = g_w3frag[(nt * 5 + c) * 32 + lane];
                mma_k32(acc, a[c][0], a[c][1], a[c][2], a[c][3], bf.x, bf.y);
            }
            {
                uint2 bf = g_w3frag[(nt * 5 + 4) * 32 + lane];
                mma_k16(acc, a40, a41, bf.x);
            }
            unsigned lo = (unsigned)(sgni(acc[0]) & 0xFF) |
                          ((unsigned)(sgni(acc[1]) & 0xFF) << 8);
            unsigned hi = (unsigned)(sgni(acc[2]) & 0xFF) |
                          ((unsigned)(sgni(acc[3]) & 0xFF) << 8);
            if (nt == 0)      { lo01 = lo;        hi01 = hi;        }
            else if (nt == 1) { lo01 |= lo << 16; hi01 |= hi << 16; }
            else if (nt == 2) { lo23 = lo;        hi23 = hi;        }
            else              { lo23 |= lo << 16; hi23 |= hi << 16; }
        }
        *(uint2*)&sepi[w][r][q * 4]     = make_uint2(lo01, lo23);
        *(uint2*)&sepi[w][r + 8][q * 4] = make_uint2(hi01, hi23);
        __syncwarp();

        if (lane < 16) {
            int gx = x0 + lane;
            if (gx < 252) {
                const uint4* rp = (const uint4*)&sepi[w][lane][0];
                size_t pix = ((size_t)b * 252 + (y0 + ry)) * 252 + gx;
                g_s3x[pix * 2 + 0] = rp[0];
                g_s3x[pix * 2 + 1] = rp[1];
            }
        }
        __syncwarp();
    }
}

// ---------------------------------------------------------------------------
// Layer 4: ternary conv (32->2) + hardtanh -> fp32 out. (R13)
// ---------------------------------------------------------------------------
__global__ __launch_bounds__(256)
void l4_kernel(float* __restrict__ out) {
    __shared__ int sw[144];
    for (int i = threadIdx.x; i < 144; i += blockDim.x) sw[i] = g_w4p[i];
    __syncthreads();
    const int4* sw4 = (const int4*)sw;               // [(o*9+pos)*2 + half]

    int b  = blockIdx.x / 63;
    int yg = blockIdx.x % 63;
    int x  = threadIdx.x;
    if (x >= 250) return;
    int y0 = yg * 4;                                 // outputs y0..y0+3 (<250)

    int acc[4][2];
    #pragma unroll
    for (int p = 0; p < 4; p++) { acc[p][0] = 0; acc[p][1] = 0; }

    #pragma unroll
    for (int cc = 0; cc < 3; cc++) {
        uint4 d[6][2];                               // rows y0..y0+5, 32B each
        #pragma unroll
        for (int r = 0; r < 6; r++) {
            int yi = y0 + r; if (yi > 251) yi = 251;
            size_t pix = ((size_t)b * 252 + yi) * 252 + (x + cc);
            d[r][0] = g_s3x[pix * 2 + 0];
            d[r][1] = g_s3x[pix * 2 + 1];
        }
        #pragma unroll
        for (int ky = 0; ky < 3; ky++)
            #pragma unroll
            for (int o = 0; o < 2; o++) {
                int4 wa = sw4[(o * 9 + ky * 3 + cc) * 2 + 0];
                int4 wb = sw4[(o * 9 + ky * 3 + cc) * 2 + 1];
                #pragma unroll
                for (int p = 0; p < 4; p++) {
                    const uint4* dr = d[ky + p];
                    acc[p][o] = __dp4a((int)dr[0].x, wa.x, acc[p][o]);
                    acc[p][o] = __dp4a((int)dr[0].y, wa.y, acc[p][o]);
                    acc[p][o] = __dp4a((int)dr[0].z, wa.z, acc[p][o]);
                    acc[p][o] = __dp4a((int)dr[0].w, wa.w, acc[p][o]);
                    acc[p][o] = __dp4a((int)dr[1].x, wb.x, acc[p][o]);
                    acc[p][o] = __dp4a((int)dr[1].y, wb.y, acc[p][o]);
                    acc[p][o] = __dp4a((int)dr[1].z, wb.z, acc[p][o]);
                    acc[p][o] = __dp4a((int)dr[1].w, wb.w, acc[p][o]);
                }
            }
    }

    #pragma unroll
    for (int p = 0; p < 4; p++) {
        if (y0 + p < 250) {
            #pragma unroll
            for (int o = 0; o < 2; o++) {
                float v = fminf(fmaxf((float)acc[p][o], -1.f), 1.f);
                out[(size_t)b * 125000 + (size_t)o * 62500 + (size_t)(y0 + p) * 250 + x] = v;
            }
        }
    }
}

// ---------------------------------------------------------------------------
extern "C" void kernel_launch(void* const* d_in, const int* in_sizes, int n_in,
                              void* d_out, int out_size) {
    const float* x  = (const float*)d_in[0];
    const float* w1 = (const float*)d_in[1];
    const float* w2 = (const float*)d_in[2];
    const float* w3 = (const float*)d_in[3];
    const float* w4 = (const float*)d_in[4];
    float* out = (float*)d_out;

    prep_kernel<<<1, 256>>>(w1, w2, w3, w4);
    l1_kernel<<<8192, 256>>>(x);                    // 32*256*256 threads
    l2_kernel<<<32 * 64, 256>>>();                  // block = (b, 4 rows)
    l3_kernel<<<32 * 63, 256>>>();                  // block = (b, 4 rows)
    l4_kernel<<<32 * 63, 256>>>(out);               // block = (b, 4 rows)
}

// round 17
// speedup vs baseline: 1.7094x; 1.0034x over previous
#include <cuda_runtime.h>
#include <cstdint>

// ---------------------------------------------------------------------------
// MCNET binarized CNN (algebraic identities, see R0):
//   * sign(maxpool(hardtanh(v))) == sign(max(v))
//   * sign(hardtanh(int n)) == sign(n)
//   * L2..L4 activations are ternary {-1,0,+1} int8 sign maps
// R17 = R15 with ALU-lean epilogues: sign bytes via IMNMX (min/max to +-1)
// + PRMT byte packing (identical bytes, ~3x fewer inst), and l3's per-tile
// column clamps removed by widening the staged tile to 260 cols (OOB cols
// feed only discarded outputs). l1 (R12), l4 (R13) frozen.
// ---------------------------------------------------------------------------

static __device__ uint2 g_s1[32u * 256 * 256];         // [b,y,x, 8ch]  16.8 MB
static __device__ int4  g_s2[32u * 254 * 254];         // [b,y,x,16ch] (perm bytes)
static __device__ uint4 g_s3x[32u * 252 * 252 * 2];    // [b,y,x][2]: 32B/px  65 MB

static __device__ float g_w1f[216];    // [o=8][c=3][ky][kx] as float +-1/0
static __device__ uint2 g_w2frag[192]; // [(nt*3+ky)*32+lane] = {b0,b1} l2 mma frags
static __device__ uint2 g_w3frag[640]; // [(nt*5+chunk)*32+lane] l3 frags (perm ch)
static __device__ int   g_w4p[144];    // [o=2][9 pos][8 words], permuted channels

__device__ __forceinline__ int sgnf(float v) { return (v > 0.f) - (v < 0.f); }
__device__ __forceinline__ int sgni(int v)   { return (v > 0) - (v < 0); }
__device__ __forceinline__ int pack4(int a, int b, int c, int d) {
    return (a & 0xFF) | ((b & 0xFF) << 8) | ((c & 0xFF) << 16) | ((d & 0xFF) << 24);
}

// ---- ALU-lean sign packing ------------------------------------------------
__device__ __forceinline__ unsigned prmt_(unsigned a, unsigned b, unsigned sel) {
    unsigned r;
    asm("prmt.b32 %0, %1, %2, %3;" : "=r"(r) : "r"(a), "r"(b), "r"(sel));
    return r;
}
// bytes [sgn(a)][sgn(b)][junk][junk]; junk discarded by the 0x5410 merge
__device__ __forceinline__ unsigned sgn_pair(int a, int b) {
    a = min(max(a, -1), 1);
    b = min(max(b, -1), 1);
    return prmt_((unsigned)a, (unsigned)b, 0x0040u);
}
// merge two u16 sign-pairs into one u32: bytes [p0.b0][p0.b1][p1.b0][p1.b1]
__device__ __forceinline__ unsigned pair_merge(unsigned p0, unsigned p1) {
    return prmt_(p0, p1, 0x5410u);
}

// ---- mma helpers ----------------------------------------------------------
__device__ __forceinline__ unsigned smem_u32(const void* p) {
    return (unsigned)__cvta_generic_to_shared(p);
}
__device__ __forceinline__ void ldmatrix_x4(unsigned& a0, unsigned& a1,
                                            unsigned& a2, unsigned& a3, unsigned addr) {
    asm volatile("ldmatrix.sync.aligned.m8n8.x4.shared.b16 {%0,%1,%2,%3}, [%4];"
                 : "=r"(a0), "=r"(a1), "=r"(a2), "=r"(a3) : "r"(addr));
}
__device__ __forceinline__ void ldmatrix_x2(unsigned& a0, unsigned& a1, unsigned addr) {
    asm volatile("ldmatrix.sync.aligned.m8n8.x2.shared.b16 {%0,%1}, [%2];"
                 : "=r"(a0), "=r"(a1) : "r"(addr));
}
__device__ __forceinline__ void mma_k32(int* c, unsigned a0, unsigned a1,
                                        unsigned a2, unsigned a3,
                                        unsigned b0, unsigned b1) {
    asm volatile("mma.sync.aligned.m16n8k32.row.col.s32.s8.s8.s32 "
                 "{%0,%1,%2,%3},{%4,%5,%6,%7},{%8,%9},{%0,%1,%2,%3};"
                 : "+r"(c[0]), "+r"(c[1]), "+r"(c[2]), "+r"(c[3])
                 : "r"(a0), "r"(a1), "r"(a2), "r"(a3), "r"(b0), "r"(b1));
}
__device__ __forceinline__ void mma_k16(int* c, unsigned a0, unsigned a1, unsigned b0) {
    asm volatile("mma.sync.aligned.m16n8k16.row.col.s32.s8.s8.s32 "
                 "{%0,%1,%2,%3},{%4,%5},{%6},{%0,%1,%2,%3};"
                 : "+r"(c[0]), "+r"(c[1]), "+r"(c[2]), "+r"(c[3])
                 : "r"(a0), "r"(a1), "r"(b0));
}

// s2 byte m holds l2-output channel perm2(m) (from l2's mma epilogue):
__device__ __forceinline__ int perm2(int m) {
    return 8 * ((m >> 1) & 1) + 2 * (m >> 2) + (m & 1);
}

// ---------------------------------------------------------------------------
__global__ void prep_kernel(const float* __restrict__ w1, const float* __restrict__ w2,
                            const float* __restrict__ w3, const float* __restrict__ w4) {
    int t = threadIdx.x;
    for (int i = t; i < 216; i += blockDim.x) g_w1f[i] = (float)sgnf(w1[i]);
    // w2 -> l2 mma B fragments. k32 chunk for ky: k = pxoff*8 + ch,
    // weight = w2[oc][ch][ky][kx=pxoff] (pxoff 3 -> 0 pad).
    for (int i = t; i < 192; i += blockDim.x) {
        int lane = i & 31, nc = i >> 5;
        int nt = nc / 3, ky = nc % 3;
        int oc = nt * 8 + (lane >> 2);
        int s0[4], s1v[4];
        #pragma unroll
        for (int j = 0; j < 4; j++) {
            int k = (lane & 3) * 4 + j;              // 0..15
            int px = k >> 3, ch = k & 7;
            s0[j] = sgnf(w2[((oc * 8 + ch) * 3 + ky) * 3 + px]);
            int k2 = k + 16;                         // 16..31
            int px2 = k2 >> 3;                       // 2 or 3
            s1v[j] = (px2 < 3) ? sgnf(w2[((oc * 8 + ch) * 3 + ky) * 3 + px2]) : 0;
        }
        g_w2frag[i] = make_uint2((unsigned)pack4(s0[0], s0[1], s0[2], s0[3]),
                                 (unsigned)pack4(s1v[0], s1v[1], s1v[2], s1v[3]));
    }
    // w3 -> mma B fragments (R11 layout, input-channel index permuted to
    // match the l2-epilogue s2 byte order).
    for (int i = t; i < 640; i += blockDim.x) {
        int lane = i & 31, nc = i >> 5;
        int nt = nc / 5, c = nc % 5;
        int oc = nt * 8 + (lane >> 2);
        int chb = (lane & 3) * 4;
        int tapA = (c < 4) ? 2 * c : 8;
        int sA[4];
        #pragma unroll
        for (int j = 0; j < 4; j++) {
            int chp = perm2(chb + j);
            sA[j] = sgnf(w3[((oc * 16 + chp) * 3 + tapA / 3) * 3 + tapA % 3]);
        }
        unsigned b0 = (unsigned)pack4(sA[0], sA[1], sA[2], sA[3]);
        unsigned b1 = 0;
        if (c < 4) {
            int tapB = 2 * c + 1;
            int sB[4];
            #pragma unroll
            for (int j = 0; j < 4; j++) {
                int chp = perm2(chb + j);
                sB[j] = sgnf(w3[((oc * 16 + chp) * 3 + tapB / 3) * 3 + tapB % 3]);
            }
            b1 = (unsigned)pack4(sB[0], sB[1], sB[2], sB[3]);
        }
        g_w3frag[i] = make_uint2(b0, b1);
    }
    // w4: s3 pixel byte m holds channel oc(m) = ((m&7)>>1)*8 + (m>>3)*2 + (m&1)
    for (int i = t; i < 144; i += blockDim.x) {
        int wrd = i & 7, pos = (i >> 3) % 9, o = i / 72;
        int ky = pos / 3, kx = pos % 3;
        int s[4];
        #pragma unroll
        for (int j = 0; j < 4; j++) {
            int m = 4 * wrd + j;
            int oc = ((m & 7) >> 1) * 8 + ((m >> 3) << 1) + (m & 1);
            s[j] = sgnf(w4[((o * 32 + oc) * 3 + ky) * 3 + kx]);
        }
        g_w4p[i] = pack4(s[0], s[1], s[2], s[3]);
    }
}

// ---------------------------------------------------------------------------
// Layer 1: fp conv (3->8), pad 1.0, fused hardtanh+maxpool+sign. (R12)
// ---------------------------------------------------------------------------
__global__ __launch_bounds__(256)
void l1_kernel(const float* __restrict__ x) {
    __shared__ __align__(16) float sw[216];          // [(c*9+ky*3+kx)*8 + o]
    for (int i = threadIdx.x; i < 216; i += 256) {
        int o = i & 7, rest = i >> 3;
        int kx = rest % 3, ky = (rest / 3) % 3, c = rest / 9;
        sw[i] = g_w1f[((o * 3 + c) * 3 + ky) * 3 + kx];
    }
    __syncthreads();
    const float4* sw4 = (const float4*)sw;           // [tap*2 + half]

    int t = blockIdx.x * blockDim.x + threadIdx.x;   // 32*256*256 threads exact
    int px = t & 255;
    int py = (t >> 8) & 255;
    int b  = t >> 16;

    float acc[4][8];
    #pragma unroll
    for (int p = 0; p < 4; p++)
        #pragma unroll
        for (int o = 0; o < 8; o++) acc[p][o] = 0.f;

    int gy0 = 2 * py - 1;
    int gx0 = 2 * px - 1;
    bool interior = (px - 1u < 254u) && (py - 1u < 254u);

    #pragma unroll
    for (int c = 0; c < 3; c++) {
        float p[4][4];
        const float* xc = x + ((size_t)b * 3 + c) * 512 * 512;
        if (interior) {
            #pragma unroll
            for (int r = 0; r < 4; r++)
                #pragma unroll
                for (int cc = 0; cc < 4; cc++)
                    p[r][cc] = __ldg(xc + (gy0 + r) * 512 + (gx0 + cc));
        } else {
            #pragma unroll
            for (int r = 0; r < 4; r++) {
                int gy = gy0 + r;
                bool rok = (unsigned)gy < 512u;
                #pragma unroll
                for (int cc = 0; cc < 4; cc++) {
                    int gx = gx0 + cc;
                    bool ok = rok && ((unsigned)gx < 512u);
                    p[r][cc] = ok ? __ldg(xc + gy * 512 + gx) : 1.0f;
                }
            }
        }
        #pragma unroll
        for (int ky = 0; ky < 3; ky++)
            #pragma unroll
            for (int kx = 0; kx < 3; kx++) {
                int tap = c * 9 + ky * 3 + kx;
                float4 wa = sw4[tap * 2 + 0];        // o = 0..3
                float4 wb = sw4[tap * 2 + 1];        // o = 4..7
                float wv[8] = {wa.x, wa.y, wa.z, wa.w, wb.x, wb.y, wb.z, wb.w};
                #pragma unroll
                for (int o = 0; o < 8; o++) {
                    float w = wv[o];
                    #pragma unroll
                    for (int dy = 0; dy < 2; dy++)
                        #pragma unroll
                        for (int dx = 0; dx < 2; dx++)
                            acc[dy * 2 + dx][o] = fmaf(p[ky + dy][kx + dx], w,
                                                       acc[dy * 2 + dx][o]);
                }
            }
    }

    int s[8];
    #pragma unroll
    for (int o = 0; o < 8; o++) {
        float m = fmaxf(fmaxf(acc[0][o], acc[1][o]), fmaxf(acc[2][o], acc[3][o]));
        s[o] = sgnf(m);
    }
    uint2 out;
    out.x = (unsigned)pack4(s[0], s[1], s[2], s[3]);
    out.y = (unsigned)pack4(s[4], s[5], s[6], s[7]);
    g_s1[((size_t)b * 256 + py) * 256 + px] = out;
}

// ---------------------------------------------------------------------------
// Layer 2: ternary conv (8->16) on int8 tensor cores.
// Block = (b, 4 output rows). Stages 6 s1 rows. Warp-tile = 16 px x 16 oc:
// 3 k32 mmas per n-tile (A row = 4 consecutive 8B pixels, kx=3 weights
// zero; fragments via LDS.32). IMNMX/PRMT sign epilogue -> STS.32;
// 16 lanes LDS.128+STG.128 into g_s2 (byte order perm2, fixed in w3frag).
// ---------------------------------------------------------------------------
__global__ __launch_bounds__(256)
void l2_kernel() {
    __shared__ __align__(16) uint2 srow[6][260];               // 8B pixel vecs
    __shared__ __align__(16) unsigned short sepi[8][16][8];    // [w][px][q*2+nt]

    int blk = blockIdx.x;
    int yg = blk & 63;
    int b  = blk >> 6;
    int y0 = yg * 4;

    for (int i = threadIdx.x; i < 6 * 256; i += 256) {
        int r = i >> 8, cx = i & 255;
        int yi = y0 + r; if (yi > 255) yi = 255;
        srow[r][cx] = g_s1[((size_t)b * 256 + yi) * 256 + cx];
    }
    // zero the 4 pad columns so A-row reads past col 255 are deterministic
    if (threadIdx.x < 24) {
        int r = threadIdx.x / 4, cx = 256 + (threadIdx.x & 3);
        srow[r][cx] = make_uint2(0u, 0u);
    }
    __syncthreads();

    int lane = threadIdx.x & 31;
    int w    = threadIdx.x >> 5;
    int q = lane & 3;
    int r = lane >> 2;

    for (int t = w; t < 64; t += 8) {
        int ry = t >> 4;
        int x0 = (t & 15) * 16;

        // A fragments per ky, built with LDS.32 (layout == ldmatrix.x4)
        unsigned a[3][4];
        #pragma unroll
        for (int ky = 0; ky < 3; ky++) {
            const char* b0 = (const char*)&srow[ry + ky][x0 + r];
            const char* b1 = (const char*)&srow[ry + ky][x0 + r + 8];
            a[ky][0] = *(const unsigned*)(b0 + q * 4);
            a[ky][1] = *(const unsigned*)(b1 + q * 4);
            a[ky][2] = *(const unsigned*)(b0 + 16 + q * 4);
            a[ky][3] = *(const unsigned*)(b1 + 16 + q * 4);
        }

        unsigned plo[2], phi[2];
        #pragma unroll
        for (int nt = 0; nt < 2; nt++) {
            int acc[4] = {0, 0, 0, 0};
            #pragma unroll
            for (int ky = 0; ky < 3; ky++) {
                uint2 bf = g_w2frag[(nt * 3 + ky) * 32 + lane];
                mma_k32(acc, a[ky][0], a[ky][1], a[ky][2], a[ky][3], bf.x, bf.y);
            }
            plo[nt] = sgn_pair(acc[0], acc[1]);
            phi[nt] = sgn_pair(acc[2], acc[3]);
        }
        *(unsigned*)&sepi[w][r][q * 2]     = pair_merge(plo[0], plo[1]);
        *(unsigned*)&sepi[w][r + 8][q * 2] = pair_merge(phi[0], phi[1]);
        __syncwarp();

        if (lane < 16) {
            int gx = x0 + lane;
            if (gx < 254 && (y0 + ry) < 254) {
                g_s2[((size_t)b * 254 + (y0 + ry)) * 254 + gx] =
                    *(const int4*)&sepi[w][lane][0];
            }
        }
        __syncwarp();
    }
}

// ---------------------------------------------------------------------------
// Layer 3: ternary conv (16->32) on int8 tensor cores.
// R17: staged tile widened to 260 cols -> no per-tile column clamps (cols
// 254..259 hold junk that feeds only discarded gx>=252 outputs; s8 has no
// NaN). IMNMX/PRMT sign epilogue. Channel perm of s2 handled in w3frag.
// ---------------------------------------------------------------------------
__global__ __launch_bounds__(256)
void l3_kernel() {
    __shared__ __align__(16) uint4 sraw[6][260];               // 16B pixel vecs
    __shared__ __align__(16) unsigned short sepi[8][16][16];   // [w][px][q*4+nt]

    int blk = blockIdx.x;
    int yg = blk % 63;
    int b  = blk / 63;
    int y0 = yg * 4;

    const uint4* src = (const uint4*)g_s2;
    for (int i = threadIdx.x; i < 6 * 254; i += 256) {
        int r = i / 254, cx = i % 254;
        sraw[r][cx] = src[((size_t)b * 254 + (y0 + r)) * 254 + cx];
    }
    __syncthreads();

    int lane = threadIdx.x & 31;
    int w    = threadIdx.x >> 5;
    int grp = lane >> 3, li = lane & 7;
    int q = lane & 3;
    int r = lane >> 2;

    for (int t = w; t < 64; t += 8) {
        int ry = t >> 4;
        int x0 = (t & 15) * 16;

        unsigned a[4][4];
        unsigned a40, a41;
        #pragma unroll
        for (int c = 0; c < 4; c++) {
            int tap = 2 * c + (grp >> 1);
            int ky = tap / 3, kx = tap % 3;
            int col = x0 + ((grp & 1) << 3) + li + kx;     // <= 257 < 260
            ldmatrix_x4(a[c][0], a[c][1], a[c][2], a[c][3],
                        smem_u32(&sraw[ry + ky][col]));
        }
        {
            int col = x0 + ((grp & 1) << 3) + li + 2;      // ky=2, kx=2
            ldmatrix_x2(a40, a41, smem_u32(&sraw[ry + 2][col]));
        }

        unsigned plo[4], phi[4];
        #pragma unroll
        for (int nt = 0; nt < 4; nt++) {
            int acc[4] = {0, 0, 0, 0};
            #pragma unroll
            for (int c = 0; c < 4; c++) {
                uint2 bf = g_w3frag[(nt * 5 + c) * 32 + lane];
                mma_k32(acc, a[c][0], a[c][1], a[c][2], a[c][3], bf.x, bf.y);
            }
            {
                uint2 bf = g_w3frag[(nt * 5 + 4) * 32 + lane];
                mma_k16(acc, a40, a41, bf.x);
            }
            plo[nt] = sgn_pair(acc[0], acc[1]);
            phi[nt] = sgn_pair(acc[2], acc[3]);
        }
        *(uint2*)&sepi[w][r][q * 4] =
            make_uint2(pair_merge(plo[0], plo[1]), pair_merge(plo[2], plo[3]));
        *(uint2*)&sepi[w][r + 8][q * 4] =
            make_uint2(pair_merge(phi[0], phi[1]), pair_merge(phi[2], phi[3]));
        __syncwarp();

        if (lane < 16) {
            int gx = x0 + lane;
            if (gx < 252) {
                const uint4* rp = (const uint4*)&sepi[w][lane][0];
                size_t pix = ((size_t)b * 252 + (y0 + ry)) * 252 + gx;
                g_s3x[pix * 2 + 0] = rp[0];
                g_s3x[pix * 2 + 1] = rp[1];
            }
        }
        __syncwarp();
    }
}

// ---------------------------------------------------------------------------
// Layer 4: ternary conv (32->2) + hardtanh -> fp32 out. (R13)
// ---------------------------------------------------------------------------
__global__ __launch_bounds__(256)
void l4_kernel(float* __restrict__ out) {
    __shared__ int sw[144];
    for (int i = threadIdx.x; i < 144; i += blockDim.x) sw[i] = g_w4p[i];
    __syncthreads();
    const int4* sw4 = (const int4*)sw;               // [(o*9+pos)*2 + half]

    int b  = blockIdx.x / 63;
    int yg = blockIdx.x % 63;
    int x  = threadIdx.x;
    if (x >= 250) return;
    int y0 = yg * 4;                                 // outputs y0..y0+3 (<250)

    int acc[4][2];
    #pragma unroll
    for (int p = 0; p < 4; p++) { acc[p][0] = 0; acc[p][1] = 0; }

    #pragma unroll
    for (int cc = 0; cc < 3; cc++) {
        uint4 d[6][2];                               // rows y0..y0+5, 32B each
        #pragma unroll
        for (int r = 0; r < 6; r++) {
            int yi = y0 + r; if (yi > 251) yi = 251;
            size_t pix = ((size_t)b * 252 + yi) * 252 + (x + cc);
            d[r][0] = g_s3x[pix * 2 + 0];
            d[r][1] = g_s3x[pix * 2 + 1];
        }
        #pragma unroll
        for (int ky = 0; ky < 3; ky++)
            #pragma unroll
            for (int o = 0; o < 2; o++) {
                int4 wa = sw4[(o * 9 + ky * 3 + cc) * 2 + 0];
                int4 wb = sw4[(o * 9 + ky * 3 + cc) * 2 + 1];
                #pragma unroll
                for (int p = 0; p < 4; p++) {
                    const uint4* dr = d[ky + p];
                    acc[p][o] = __dp4a((int)dr[0].x, wa.x, acc[p][o]);
                    acc[p][o] = __dp4a((int)dr[0].y, wa.y, acc[p][o]);
                    acc[p][o] = __dp4a((int)dr[0].z, wa.z, acc[p][o]);
                    acc[p][o] = __dp4a((int)dr[0].w, wa.w, acc[p][o]);
                    acc[p][o] = __dp4a((int)dr[1].x, wb.x, acc[p][o]);
                    acc[p][o] = __dp4a((int)dr[1].y, wb.y, acc[p][o]);
                    acc[p][o] = __dp4a((int)dr[1].z, wb.z, acc[p][o]);
                    acc[p][o] = __dp4a((int)dr[1].w, wb.w, acc[p][o]);
                }
            }
    }

    #pragma unroll
    for (int p = 0; p < 4; p++) {
        if (y0 + p < 250) {
            #pragma unroll
            for (int o = 0; o < 2; o++) {
                float v = fminf(fmaxf((float)acc[p][o], -1.f), 1.f);
                out[(size_t)b * 125000 + (size_t)o * 62500 + (size_t)(y0 + p) * 250 + x] = v;
            }
        }
    }
}

// ---------------------------------------------------------------------------
extern "C" void kernel_launch(void* const* d_in, const int* in_sizes, int n_in,
                              void* d_out, int out_size) {
    const float* x  = (const float*)d_in[0];
    const float* w1 = (const float*)d_in[1];
    const float* w2 = (const float*)d_in[2];
    const float* w3 = (const float*)d_in[3];
    const float* w4 = (const float*)d_in[4];
    float* out = (float*)d_out;

    prep_kernel<<<1, 256>>>(w1, w2, w3, w4);
    l1_kernel<<<8192, 256>>>(x);                    // 32*256*256 threads
    l2_kernel<<<32 * 64, 256>>>();                  // block = (b, 4 rows)
    l3_kernel<<<32 * 63, 256>>>();                  // block = (b, 4 rows)
    l4_kernel<<<32 * 63, 256>>>(out);               // block = (b, 4 rows)
}